// round 12
// baseline (speedup 1.0000x reference)
#include <cuda_runtime.h>
#include <cuda_bf16.h>
#include <math.h>
#include <stdint.h>

#define Bb   8
#define Cc   256
#define Nn   2304
#define Mtot (Bb*Nn)
#define NMB  (Nn/128)      // 18 n-blocks per batch row-range
#define EPSf 1e-5f

// ---------------------------------------------------------------------------
// Scratch
// ---------------------------------------------------------------------------
__device__ __align__(128) __nv_bfloat16 g_xb[2][(size_t)Bb*Cc*Nn];   // bf16 X [p][b][c][n]
__device__ __align__(128) __nv_bfloat16 g_wb[6][(size_t)Cc*Cc];      // bf16 W
__device__ __align__(128) __nv_bfloat16 g_q[2][(size_t)Mtot*Cc];
__device__ __align__(128) __nv_bfloat16 g_k[2][(size_t)Mtot*Cc];
__device__ __align__(128) __nv_bfloat16 g_v[2][(size_t)Mtot*Cc];
__device__ __align__(128) __nv_bfloat16 g_attnb[(size_t)Bb*Nn*Nn];   // bf16 exp(S)
__device__ __align__(128) float g_psum[(size_t)Bb*NMB*Nn];           // partial row sums
__device__ __align__(128) float g_rinv[(size_t)Mtot];                // 1/rowsum
__device__ __align__(128) __nv_bfloat16 g_outT[2][(size_t)Bb*Cc*Nn]; // bf16 [p][b][c][n]
__device__ __align__(128) float g_bnps[2][Cc][Bb*NMB][2];            // per-(c, b*18+nblk) partial (sum, sumsq)
__device__ float g_mean[2][Cc];
__device__ float g_rstd[2][Cc];

// ---------------------------------------------------------------------------
// helpers
// ---------------------------------------------------------------------------
__device__ __forceinline__ uint32_t s2u(const void* p){
    return (uint32_t)__cvta_generic_to_shared(p);
}
__device__ __forceinline__ uint32_t packbf(float lo, float hi){
    uint32_t r;
    asm("cvt.rn.bf16x2.f32 %0, %1, %2;" : "=r"(r) : "f"(hi), "f"(lo));
    return r;
}
__device__ __forceinline__ void mma16(float* d, const uint32_t* a, const uint32_t* b){
    asm volatile("mma.sync.aligned.m16n8k16.row.col.f32.bf16.bf16.f32 "
        "{%0,%1,%2,%3}, {%4,%5,%6,%7}, {%8,%9}, {%0,%1,%2,%3};"
        : "+f"(d[0]),"+f"(d[1]),"+f"(d[2]),"+f"(d[3])
        : "r"(a[0]),"r"(a[1]),"r"(a[2]),"r"(a[3]),"r"(b[0]),"r"(b[1]));
}
__device__ __forceinline__ void ldsm4(uint32_t* r, uint32_t addr){
    asm volatile("ldmatrix.sync.aligned.m8n8.x4.shared.b16 {%0,%1,%2,%3}, [%4];"
        : "=r"(r[0]),"=r"(r[1]),"=r"(r[2]),"=r"(r[3]) : "r"(addr));
}
__device__ __forceinline__ void ldsm4t(uint32_t* r, uint32_t addr){
    asm volatile("ldmatrix.sync.aligned.m8n8.x4.trans.shared.b16 {%0,%1,%2,%3}, [%4];"
        : "=r"(r[0]),"=r"(r[1]),"=r"(r[2]),"=r"(r[3]) : "r"(addr));
}
__device__ __forceinline__ void cpa16(uint32_t dst, const void* src){
    asm volatile("cp.async.cg.shared.global [%0], [%1], 16;" :: "r"(dst), "l"(src));
}
#define CP_COMMIT() asm volatile("cp.async.commit_group;")
#define CP_WAIT(N)  asm volatile("cp.async.wait_group %0;" :: "n"(N))

// 64B-row smem tile: swizzled 16B-chunk offset
__device__ __forceinline__ uint32_t sw64(uint32_t tile, int r, int c16){
    return tile + (uint32_t)r*64u + (uint32_t)((c16 ^ ((r>>1)&3))<<4);
}
// 128B-row smem tile: swizzled 16B-chunk offset (8 chunks/row)
__device__ __forceinline__ uint32_t sw128(uint32_t tile, int r, int c16){
    return tile + (uint32_t)r*128u + (uint32_t)((c16 ^ (r&7))<<4);
}

// ---------------------------------------------------------------------------
// Kernel 0: convert X (both parts) and 6 weight matrices fp32 -> bf16
//   Grid split: first XBLKS blocks do X, remainder do W.
// ---------------------------------------------------------------------------
#define XBLKS ((2*(size_t)Bb*Cc*Nn/8)/256)    // 4608
#define WBLKS ((6*Cc*Cc/8)/256)               // 192

__global__ void __launch_bounds__(256) k_cvtall(
    const float* __restrict__ xr, const float* __restrict__ xi,
    const float* __restrict__ qwr, const float* __restrict__ qwi,
    const float* __restrict__ kwr, const float* __restrict__ kwi,
    const float* __restrict__ vwr, const float* __restrict__ vwi)
{
    if (blockIdx.x < XBLKS) {
        const size_t i8 = ((size_t)blockIdx.x*256 + threadIdx.x) * 8;
        const size_t half = (size_t)Bb*Cc*Nn;
        const int p = (i8 >= half) ? 1 : 0;
        const size_t rem = i8 - (size_t)p*half;
        const float* x = p ? xi : xr;
        float4 a = *(const float4*)(x + rem);
        float4 b = *(const float4*)(x + rem + 4);
        uint4 o;
        o.x = packbf(a.x,a.y); o.y = packbf(a.z,a.w);
        o.z = packbf(b.x,b.y); o.w = packbf(b.z,b.w);
        *(uint4*)(g_xb[p] + rem) = o;
    } else {
        const float* mats[6] = { qwr, qwi, kwr, kwi, vwr, vwi };
        const int i8 = ((blockIdx.x - (int)XBLKS)*256 + threadIdx.x) * 8;
        const int mat = i8 >> 16;
        const int rem = i8 & 65535;
        const float* src = mats[mat];
        float4 a = *(const float4*)(src + rem);
        float4 b = *(const float4*)(src + rem + 4);
        uint4 o;
        o.x = packbf(a.x,a.y); o.y = packbf(a.z,a.w);
        o.z = packbf(b.x,b.y); o.w = packbf(b.z,b.w);
        *(uint4*)(g_wb[mat] + rem) = o;
    }
}

// ---------------------------------------------------------------------------
// Kernel 1: complex projection, cp.async 3-stage ring, K-step 32.
// ---------------------------------------------------------------------------
#define PJ_XPART 8704
#define PJ_WOFF  17408
#define PJ_WPART 4096
#define PJ_STAGE 25600
#define PJ_SMEM  (3*PJ_STAGE)

__global__ void __launch_bounds__(256) k_proj(
    const float* __restrict__ qbr, const float* __restrict__ qbi,
    const float* __restrict__ kbr, const float* __restrict__ kbi,
    const float* __restrict__ vbr, const float* __restrict__ vbi)
{
    extern __shared__ __align__(16) unsigned char dyn[];
    const uint32_t base = s2u(dyn);

    const int wsel = blockIdx.z;
    const float* brv = (wsel==0)?qbr:(wsel==1)?kbr:vbr;
    const float* biv = (wsel==0)?qbi:(wsel==1)?kbi:vbi;
    __nv_bfloat16* yr = (wsel==0)?g_q[0]:(wsel==1)?g_k[0]:g_v[0];
    __nv_bfloat16* yi = (wsel==0)?g_q[1]:(wsel==1)?g_k[1]:g_v[1];

    const int tid = threadIdx.x;
    const int w = tid >> 5, lane = tid & 31;
    const int gr = lane >> 2, tg = lane & 3;
    const int wm = w & 3, wn = w >> 2;
    const int m0 = blockIdx.x * 128;
    const int d0 = blockIdx.y * 64;
    const int b  = m0 / Nn;
    const int n0 = m0 - b*Nn;

    const __nv_bfloat16* xbp[2] = { g_xb[0] + (size_t)b*Cc*Nn, g_xb[1] + (size_t)b*Cc*Nn };
    const __nv_bfloat16* wbp[2] = { g_wb[wsel*2], g_wb[wsel*2+1] };

    float accr[2][4][4], acci[2][4][4];
    #pragma unroll
    for (int mf=0; mf<2; ++mf)
        #pragma unroll
        for (int nf=0; nf<4; ++nf)
            #pragma unroll
            for (int e=0; e<4; ++e){ accr[mf][nf][e]=0.f; acci[mf][nf][e]=0.f; }

    auto load_stage = [&](int s, int ck){
        const uint32_t st = base + s*PJ_STAGE;
        #pragma unroll
        for (int it=0; it<4; ++it){
            int idx = tid + 256*it;
            int p = idx>>9, r = (idx>>4)&31, c = idx&15;
            cpa16(st + p*PJ_XPART + r*272 + c*16,
                  xbp[p] + (size_t)(ck+r)*Nn + n0 + c*8);
        }
        #pragma unroll
        for (int it=0; it<2; ++it){
            int idx = tid + 256*it;
            int p = idx>>8, r = (idx>>2)&63, c = idx&3;
            cpa16(sw64(st + PJ_WOFF + p*PJ_WPART, r, c),
                  wbp[p] + (size_t)(d0+r)*Cc + ck + c*8);
        }
        CP_COMMIT();
    };

    load_stage(0, 0);
    load_stage(1, 32);

    for (int kt = 0; kt < 8; ++kt) {
        const int s = kt % 3;
        if (kt < 7) { CP_WAIT(1); } else { CP_WAIT(0); }
        __syncthreads();
        if (kt + 2 < 8) load_stage((kt+2)%3, (kt+2)*32);

        const uint32_t st = base + s*PJ_STAGE;
        #pragma unroll
        for (int ks=0; ks<32; ks+=16) {
            uint32_t axr[2][4], axi[2][4], ain[2][4];
            #pragma unroll
            for (int mf=0; mf<2; ++mf) {
                int crow = ks + (lane&7) + (lane>>4)*8;
                int mcol = wm*32 + mf*16 + ((lane>>3)&1)*8;
                ldsm4t(axr[mf], st + 0*PJ_XPART + (uint32_t)crow*272 + (uint32_t)mcol*2);
                ldsm4t(axi[mf], st + 1*PJ_XPART + (uint32_t)crow*272 + (uint32_t)mcol*2);
                #pragma unroll
                for (int e=0;e<4;++e) ain[mf][e] = axi[mf][e] ^ 0x80008000u;
            }
            #pragma unroll
            for (int nf2=0; nf2<2; ++nf2) {
                int rr = wn*32 + nf2*16 + (lane>>4)*8 + (lane&7);
                int c16 = (ks>>3) + ((lane>>3)&1);
                uint32_t bwr[4], bwi[4];
                ldsm4(bwr, sw64(st + PJ_WOFF,            rr, c16));
                ldsm4(bwi, sw64(st + PJ_WOFF + PJ_WPART, rr, c16));
                #pragma unroll
                for (int h=0; h<2; ++h) {
                    int nfr = nf2*2 + h;
                    #pragma unroll
                    for (int mf=0; mf<2; ++mf) {
                        mma16(accr[mf][nfr], axr[mf], bwr + 2*h);
                        mma16(accr[mf][nfr], ain[mf], bwi + 2*h);
                        mma16(acci[mf][nfr], axr[mf], bwi + 2*h);
                        mma16(acci[mf][nfr], axi[mf], bwr + 2*h);
                    }
                }
            }
        }
        __syncthreads();
    }

    #pragma unroll
    for (int mf=0; mf<2; ++mf) {
        const int row0 = m0 + wm*32 + mf*16 + gr;
        #pragma unroll
        for (int nfr=0; nfr<4; ++nfr) {
            const int col0 = d0 + wn*32 + nfr*8 + 2*tg;
            const float b0r = brv[col0], b1r = brv[col0+1];
            const float b0i = biv[col0], b1i = biv[col0+1];
            *(uint32_t*)&yr[(size_t)row0*Cc + col0]     = packbf(accr[mf][nfr][0]+b0r, accr[mf][nfr][1]+b1r);
            *(uint32_t*)&yr[(size_t)(row0+8)*Cc + col0] = packbf(accr[mf][nfr][2]+b0r, accr[mf][nfr][3]+b1r);
            *(uint32_t*)&yi[(size_t)row0*Cc + col0]     = packbf(acci[mf][nfr][0]+b0i, acci[mf][nfr][1]+b1i);
            *(uint32_t*)&yi[(size_t)(row0+8)*Cc + col0] = packbf(acci[mf][nfr][2]+b0i, acci[mf][nfr][3]+b1i);
        }
    }
}

// ---------------------------------------------------------------------------
// Kernel 2: scores + exp. Block 128n x 128m, warps 2(n)x4(m), warp 64x32.
// ---------------------------------------------------------------------------
#define SC_STAGE 32768
#define SC_SMEM  (3*SC_STAGE)

__global__ void __launch_bounds__(256) k_scores()
{
    extern __shared__ __align__(16) unsigned char dyn[];
    const uint32_t base = s2u(dyn);

    const int tid = threadIdx.x;
    const int w = tid >> 5, lane = tid & 31;
    const int gr = lane >> 2, tg = lane & 3;
    const int wrow = w & 1, wcol = w >> 1;
    const int m0 = blockIdx.x * 128;
    const int n0 = blockIdx.y * 128;
    const int b  = blockIdx.z;

    const __nv_bfloat16* srcs[4] = {
        g_q[0] + (size_t)b*Nn*Cc, g_q[1] + (size_t)b*Nn*Cc,
        g_k[0] + (size_t)b*Nn*Cc, g_k[1] + (size_t)b*Nn*Cc };
    const int rbase[4] = { n0, n0, m0, m0 };

    float acc[4][4][4];
    #pragma unroll
    for (int mf=0; mf<4; ++mf)
        #pragma unroll
        for (int nf=0; nf<4; ++nf)
            #pragma unroll
            for (int e=0; e<4; ++e) acc[mf][nf][e]=0.f;

    auto load_stage = [&](int s, int ck){
        const uint32_t st = base + s*SC_STAGE;
        #pragma unroll
        for (int t=0;t<4;++t){
            const uint32_t tb = st + t*8192;
            #pragma unroll
            for (int it=0; it<2; ++it){
                int idx = tid + 256*it;
                int r = idx>>2, c = idx&3;
                cpa16(sw64(tb, r, c), srcs[t] + (size_t)(rbase[t]+r)*Cc + ck + c*8);
            }
        }
        CP_COMMIT();
    };

    load_stage(0, 0);
    load_stage(1, 32);

    for (int kt = 0; kt < 8; ++kt) {
        const int s = kt % 3;
        if (kt < 7) { CP_WAIT(1); } else { CP_WAIT(0); }
        __syncthreads();
        if (kt + 2 < 8) load_stage((kt+2)%3, (kt+2)*32);

        const uint32_t st = base + s*SC_STAGE;
        #pragma unroll
        for (int p=0; p<2; ++p) {
            const uint32_t qt = st + p*8192;
            const uint32_t ktile = st + 16384 + p*8192;
            #pragma unroll
            for (int ks=0; ks<32; ks+=16) {
                uint32_t a[4][4];
                #pragma unroll
                for (int mf=0; mf<4; ++mf) {
                    int r = wrow*64 + mf*16 + (lane&15);
                    int c16 = (ks>>3) + (lane>>4);
                    ldsm4(a[mf], sw64(qt, r, c16));
                }
                #pragma unroll
                for (int nf2=0; nf2<2; ++nf2) {
                    int rr = wcol*32 + nf2*16 + (lane>>4)*8 + (lane&7);
                    int c16 = (ks>>3) + ((lane>>3)&1);
                    uint32_t bb[4];
                    ldsm4(bb, sw64(ktile, rr, c16));
                    #pragma unroll
                    for (int mf=0; mf<4; ++mf) {
                        mma16(acc[mf][nf2*2  ], a[mf], bb);
                        mma16(acc[mf][nf2*2+1], a[mf], bb+2);
                    }
                }
            }
        }
        __syncthreads();
    }

    // epilogue: exp + store + deterministic partial row sums
    float (*spsum)[128] = (float(*)[128])dyn;
    const float sc = 1.0f/16.0f;
    #pragma unroll
    for (int mf=0; mf<4; ++mf) {
        const int row0 = n0 + wrow*64 + mf*16 + gr;
        const size_t r0b = (size_t)b*Nn*Nn + (size_t)row0*Nn;
        const size_t r1b = r0b + (size_t)8*Nn;
        float p0 = 0.f, p1 = 0.f;
        #pragma unroll
        for (int nfr=0; nfr<4; ++nfr) {
            const int col0 = m0 + wcol*32 + nfr*8 + 2*tg;
            float e0 = __expf(acc[mf][nfr][0]*sc);
            float e1 = __expf(acc[mf][nfr][1]*sc);
            float e2 = __expf(acc[mf][nfr][2]*sc);
            float e3 = __expf(acc[mf][nfr][3]*sc);
            *(uint32_t*)&g_attnb[r0b + col0] = packbf(e0, e1);
            *(uint32_t*)&g_attnb[r1b + col0] = packbf(e2, e3);
            p0 += e0 + e1;
            p1 += e2 + e3;
        }
        p0 += __shfl_xor_sync(0xFFFFFFFFu, p0, 1);
        p0 += __shfl_xor_sync(0xFFFFFFFFu, p0, 2);
        p1 += __shfl_xor_sync(0xFFFFFFFFu, p1, 1);
        p1 += __shfl_xor_sync(0xFFFFFFFFu, p1, 2);
        if (tg == 0) {
            spsum[wcol][wrow*64 + mf*16 + gr    ] = p0;
            spsum[wcol][wrow*64 + mf*16 + gr + 8] = p1;
        }
    }
    __syncthreads();
    if (tid < 128) {
        float s4 = spsum[0][tid] + spsum[1][tid] + spsum[2][tid] + spsum[3][tid];
        g_psum[((size_t)b*NMB + (m0>>7))*Nn + n0 + tid] = s4;
    }
}

// ---------------------------------------------------------------------------
// Kernel 3: row-sum reduce -> 1/sum
// ---------------------------------------------------------------------------
__global__ void __launch_bounds__(256) k_rowsum()
{
    const int i = blockIdx.x*256 + threadIdx.x;
    const int b = i / Nn, n = i - b*Nn;
    float s = 0.f;
    #pragma unroll
    for (int mb=0; mb<NMB; ++mb)
        s += g_psum[((size_t)b*NMB + mb)*Nn + n];
    g_rinv[i] = 1.f / s;
}

// ---------------------------------------------------------------------------
// Kernel 4: AV + fused BN partial stats. Block 128n x 64d, 3-stage, K-step 64.
// ---------------------------------------------------------------------------
#define AV_VOFF  16384
#define AV_STAGE (16384 + 18432)   // 34816
#define AV_SMEM  (3*AV_STAGE)      // 104448

__global__ void __launch_bounds__(256) k_av(
    const float* __restrict__ xr, const float* __restrict__ xi,
    const float* __restrict__ gamma)
{
    extern __shared__ __align__(16) unsigned char dyn[];
    const uint32_t base = s2u(dyn);

    const int tid = threadIdx.x;
    const int w = tid >> 5, lane = tid & 31;
    const int gr = lane >> 2, tg = lane & 3;
    const int wm = w & 3, wn = w >> 2;
    const int n0 = blockIdx.x * 128;
    const int d0 = blockIdx.y * 64;
    const int b  = blockIdx.z;

    const __nv_bfloat16* Ab  = g_attnb + (size_t)b*Nn*Nn;
    const __nv_bfloat16* vp[2] = { g_v[0] + (size_t)b*Nn*Cc, g_v[1] + (size_t)b*Nn*Cc };

    float accr[2][4][4], acci[2][4][4];
    #pragma unroll
    for (int mf=0; mf<2; ++mf)
        #pragma unroll
        for (int nf=0; nf<4; ++nf)
            #pragma unroll
            for (int e=0; e<4; ++e){ accr[mf][nf][e]=0.f; acci[mf][nf][e]=0.f; }

    auto load_stage = [&](int s, int mk){
        const uint32_t st = base + s*AV_STAGE;
        #pragma unroll
        for (int it=0; it<4; ++it){
            int idx = tid + 256*it;
            int r = idx>>3, c = idx&7;
            cpa16(sw128(st, r, c), Ab + (size_t)(n0+r)*Nn + mk + c*8);
        }
        #pragma unroll
        for (int it=0; it<4; ++it){
            int idx = tid + 256*it;
            int p = idx>>9, r = (idx>>3)&63, c = idx&7;
            cpa16(st + AV_VOFF + p*9216 + r*144 + c*16,
                  vp[p] + (size_t)(mk+r)*Cc + d0 + c*8);
        }
        CP_COMMIT();
    };

    load_stage(0, 0);
    load_stage(1, 64);

    const int NKT = Nn/64;   // 36
    for (int kt = 0; kt < NKT; ++kt) {
        const int s = kt % 3;
        if (kt < NKT-1) { CP_WAIT(1); } else { CP_WAIT(0); }
        __syncthreads();
        if (kt + 2 < NKT) load_stage((kt+2)%3, (kt+2)*64);

        const uint32_t st = base + s*AV_STAGE;
        #pragma unroll
        for (int ks=0; ks<64; ks+=16) {
            uint32_t a[2][4];
            #pragma unroll
            for (int mf=0; mf<2; ++mf) {
                int r = wm*32 + mf*16 + (lane&15);
                int c16 = (ks>>3) + (lane>>4);
                ldsm4(a[mf], sw128(st, r, c16));
            }
            #pragma unroll
            for (int nf2=0; nf2<2; ++nf2) {
                int cb = wn*32 + nf2*16;
                uint32_t bvr[4], bvi[4];
                uint32_t vaddr = st + AV_VOFF + (uint32_t)(ks + (lane&15))*144 + (uint32_t)(cb + (lane>>4)*8)*2;
                ldsm4t(bvr, vaddr);
                ldsm4t(bvi, vaddr + 9216);
                #pragma unroll
                for (int h=0; h<2; ++h) {
                    int nfr = nf2*2 + h;
                    #pragma unroll
                    for (int mf=0; mf<2; ++mf) {
                        mma16(accr[mf][nfr], a[mf], bvr + 2*h);
                        mma16(acci[mf][nfr], a[mf], bvi + 2*h);
                    }
                }
            }
        }
        __syncthreads();
    }

    float rin[2][2];
    #pragma unroll
    for (int mf=0; mf<2; ++mf) {
        rin[mf][0] = g_rinv[(size_t)b*Nn + n0 + wm*32 + mf*16 + gr];
        rin[mf][1] = g_rinv[(size_t)b*Nn + n0 + wm*32 + mf*16 + gr + 8];
    }
    const float gma = gamma[0];

    // transpose epilogue -> g_outT [d][n] bf16, + fused BN partial stats
    __nv_bfloat16 (*stage)[144] = (__nv_bfloat16(*)[144])dyn;
    const size_t basep = (size_t)b*Cc*Nn + (size_t)d0*Nn + n0;
    #pragma unroll
    for (int p=0; p<2; ++p) {
        __syncthreads();
        #pragma unroll
        for (int mf=0; mf<2; ++mf) {
            int rl = wm*32 + mf*16 + gr;
            #pragma unroll
            for (int nfr=0; nfr<4; ++nfr) {
                int cl = wn*32 + nfr*8 + 2*tg;
                float* acc = p ? acci[mf][nfr] : accr[mf][nfr];
                stage[cl  ][rl  ] = __float2bfloat16(acc[0]*rin[mf][0]);
                stage[cl+1][rl  ] = __float2bfloat16(acc[1]*rin[mf][0]);
                stage[cl  ][rl+8] = __float2bfloat16(acc[2]*rin[mf][1]);
                stage[cl+1][rl+8] = __float2bfloat16(acc[3]*rin[mf][1]);
            }
        }
        __syncthreads();
        #pragma unroll
        for (int it=0; it<4; ++it) {
            int idx = tid + 256*it;
            int dl = idx >> 4, c8 = idx & 15;
            *(uint4*)(g_outT[p] + basep + (size_t)dl*Nn + c8*8) = *(const uint4*)&stage[dl][c8*8];
        }
        // BN partial stats: z = x + gamma*out (out = bf16 staged value, matching
        // what bnapply will read). 4 threads per d-row, 32 n each, shfl reduce.
        {
            const float* x = p ? xi : xr;
            const int dl = tid >> 2;           // 0..63
            const int nq = (tid & 3) * 32;     // 0/32/64/96
            const float* xrow = x + (size_t)b*Cc*Nn + (size_t)(d0+dl)*Nn + n0 + nq;
            float s = 0.f, ss = 0.f;
            #pragma unroll
            for (int i=0; i<32; ++i) {
                float z = xrow[i] + gma * __bfloat162float(stage[dl][nq+i]);
                s += z; ss += z*z;
            }
            s  += __shfl_xor_sync(0xFFFFFFFFu, s, 1);
            s  += __shfl_xor_sync(0xFFFFFFFFu, s, 2);
            ss += __shfl_xor_sync(0xFFFFFFFFu, ss, 1);
            ss += __shfl_xor_sync(0xFFFFFFFFu, ss, 2);
            if ((tid & 3) == 0) {
                const int wi = b*NMB + blockIdx.x;   // 0..143
                g_bnps[p][d0+dl][wi][0] = s;
                g_bnps[p][d0+dl][wi][1] = ss;
            }
        }
    }
}

// ---------------------------------------------------------------------------
// Kernel 5: BN stats reduce (144 partials per channel) -> mean, rstd
// ---------------------------------------------------------------------------
__global__ void __launch_bounds__(256) k_bnred()
{
    const int c = blockIdx.x, p = blockIdx.y;
    const int tid = threadIdx.x;
    float s = 0.f, ss = 0.f;
    if (tid < Bb*NMB) {
        s  = g_bnps[p][c][tid][0];
        ss = g_bnps[p][c][tid][1];
    }
    __shared__ float rs[256], rss[256];
    rs[tid] = s; rss[tid] = ss; __syncthreads();
    #pragma unroll
    for (int st = 128; st > 0; st >>= 1) {
        if (tid < st) { rs[tid] += rs[tid+st]; rss[tid] += rss[tid+st]; }
        __syncthreads();
    }
    if (tid == 0) {
        const float inv_cnt = 1.f / (float)Mtot;
        float mean = rs[0] * inv_cnt;
        float var  = rss[0] * inv_cnt - mean*mean;
        g_mean[p][c] = mean;
        g_rstd[p][c] = rsqrtf(var + EPSf);
    }
}

// ---------------------------------------------------------------------------
// Kernel 6: BN apply
// ---------------------------------------------------------------------------
__global__ void __launch_bounds__(256) k_bnapply(
    const float* __restrict__ xr, const float* __restrict__ xi,
    const float* __restrict__ gamma,
    const float* __restrict__ bnwr, const float* __restrict__ bnbr,
    const float* __restrict__ bnwi, const float* __restrict__ bnbi,
    float* __restrict__ out)
{
    const int idx4 = blockIdx.x*256 + threadIdx.x;
    const size_t e = (size_t)idx4 * 4;
    const size_t half = (size_t)Bb*Cc*Nn;
    const int p = (e >= half) ? 1 : 0;
    const size_t rem = e - (size_t)p*half;
    const int c = (int)((rem / Nn) % Cc);

    const float* x = p ? xi : xr;
    const float g = gamma[0];
    const float wsc = (p ? bnwi[c] : bnwr[c]) * g_rstd[p][c];
    const float bia = (p ? bnbi[c] : bnbr[c]);
    const float mu = g_mean[p][c];

    float4 xv = *(const float4*)(x + rem);
    uint2 ou = *(const uint2*)(g_outT[p] + rem);
    float2 o01 = __bfloat1622float2(*reinterpret_cast<const __nv_bfloat162*>(&ou.x));
    float2 o23 = __bfloat1622float2(*reinterpret_cast<const __nv_bfloat162*>(&ou.y));

    float4 r;
    r.x = (xv.x + g*o01.x - mu) * wsc + bia;
    r.y = (xv.y + g*o01.y - mu) * wsc + bia;
    r.z = (xv.z + g*o23.x - mu) * wsc + bia;
    r.w = (xv.w + g*o23.y - mu) * wsc + bia;
    *(float4*)(out + e) = r;
}

// ---------------------------------------------------------------------------
// Launch
// ---------------------------------------------------------------------------
extern "C" void kernel_launch(void* const* d_in, const int* in_sizes, int n_in,
                              void* d_out, int out_size)
{
    const float* xr   = (const float*)d_in[0];
    const float* xi   = (const float*)d_in[1];
    const float* q_wr = (const float*)d_in[2];
    const float* q_wi = (const float*)d_in[3];
    const float* q_br = (const float*)d_in[4];
    const float* q_bi = (const float*)d_in[5];
    const float* k_wr = (const float*)d_in[6];
    const float* k_wi = (const float*)d_in[7];
    const float* k_br = (const float*)d_in[8];
    const float* k_bi = (const float*)d_in[9];
    const float* v_wr = (const float*)d_in[10];
    const float* v_wi = (const float*)d_in[11];
    const float* v_br = (const float*)d_in[12];
    const float* v_bi = (const float*)d_in[13];
    const float* gamma= (const float*)d_in[14];
    const float* bnwr = (const float*)d_in[15];
    const float* bnbr = (const float*)d_in[16];
    const float* bnwi = (const float*)d_in[17];
    const float* bnbi = (const float*)d_in[18];
    float* out = (float*)d_out;

    cudaFuncSetAttribute(k_proj,   cudaFuncAttributeMaxDynamicSharedMemorySize, PJ_SMEM);
    cudaFuncSetAttribute(k_scores, cudaFuncAttributeMaxDynamicSharedMemorySize, SC_SMEM);
    cudaFuncSetAttribute(k_av,     cudaFuncAttributeMaxDynamicSharedMemorySize, AV_SMEM);

    k_cvtall<<<(unsigned)(XBLKS + WBLKS), 256>>>(xr, xi, q_wr, q_wi, k_wr, k_wi, v_wr, v_wi);

    k_proj<<<dim3(Mtot/128, Cc/64, 3), 256, PJ_SMEM>>>(q_br, q_bi, k_br, k_bi, v_br, v_bi);

    k_scores<<<dim3(Nn/128, Nn/128, Bb), 256, SC_SMEM>>>();
    k_rowsum<<<Mtot/256, 256>>>();
    k_av<<<dim3(Nn/128, Cc/64, Bb), 256, AV_SMEM>>>(xr, xi, gamma);

    k_bnred<<<dim3(Cc, 2), 256>>>();
    k_bnapply<<<(2*(size_t)Bb*Cc*Nn/4)/256, 256>>>(xr, xi, gamma, bnwr, bnbr, bnwi, bnbi, out);
}

// round 13
// speedup vs baseline: 1.1088x; 1.1088x over previous
#include <cuda_runtime.h>
#include <cuda_bf16.h>
#include <math.h>
#include <stdint.h>

#define Bb   8
#define Cc   256
#define Nn   2304
#define Mtot (Bb*Nn)
#define NMB  (Nn/128)      // 18 n-blocks
#define EPSf 1e-5f

// ---------------------------------------------------------------------------
// Scratch
// ---------------------------------------------------------------------------
__device__ __align__(128) __nv_bfloat16 g_xb[2][(size_t)Bb*Cc*Nn];   // bf16 X [p][b][c][n]
__device__ __align__(128) __nv_bfloat16 g_wb[6][(size_t)Cc*Cc];      // bf16 W
__device__ __align__(128) __nv_bfloat16 g_q[2][(size_t)Mtot*Cc];
__device__ __align__(128) __nv_bfloat16 g_k[2][(size_t)Mtot*Cc];
__device__ __align__(128) __nv_bfloat16 g_v[2][(size_t)Mtot*Cc];
__device__ __align__(128) __nv_bfloat16 g_attnb[(size_t)Bb*Nn*Nn];   // bf16 exp(S)
__device__ __align__(128) float g_psum[(size_t)Bb*NMB*Nn];           // partial row sums
__device__ __align__(128) float g_rinv[(size_t)Mtot];                // 1/rowsum
__device__ __align__(128) __nv_bfloat16 g_outT[2][(size_t)Bb*Cc*Nn]; // bf16 [p][b][c][n]
__device__ __align__(128) float g_bnps[2][Cc][Bb*NMB][2];            // per-(c, b*18+nblk) (sum, sumsq)
__device__ float g_mean[2][Cc];
__device__ float g_rstd[2][Cc];

// ---------------------------------------------------------------------------
// helpers
// ---------------------------------------------------------------------------
__device__ __forceinline__ uint32_t s2u(const void* p){
    return (uint32_t)__cvta_generic_to_shared(p);
}
__device__ __forceinline__ uint32_t packbf(float lo, float hi){
    uint32_t r;
    asm("cvt.rn.bf16x2.f32 %0, %1, %2;" : "=r"(r) : "f"(hi), "f"(lo));
    return r;
}
__device__ __forceinline__ void mma16(float* d, const uint32_t* a, const uint32_t* b){
    asm volatile("mma.sync.aligned.m16n8k16.row.col.f32.bf16.bf16.f32 "
        "{%0,%1,%2,%3}, {%4,%5,%6,%7}, {%8,%9}, {%0,%1,%2,%3};"
        : "+f"(d[0]),"+f"(d[1]),"+f"(d[2]),"+f"(d[3])
        : "r"(a[0]),"r"(a[1]),"r"(a[2]),"r"(a[3]),"r"(b[0]),"r"(b[1]));
}
__device__ __forceinline__ void ldsm4(uint32_t* r, uint32_t addr){
    asm volatile("ldmatrix.sync.aligned.m8n8.x4.shared.b16 {%0,%1,%2,%3}, [%4];"
        : "=r"(r[0]),"=r"(r[1]),"=r"(r[2]),"=r"(r[3]) : "r"(addr));
}
__device__ __forceinline__ void ldsm4t(uint32_t* r, uint32_t addr){
    asm volatile("ldmatrix.sync.aligned.m8n8.x4.trans.shared.b16 {%0,%1,%2,%3}, [%4];"
        : "=r"(r[0]),"=r"(r[1]),"=r"(r[2]),"=r"(r[3]) : "r"(addr));
}
__device__ __forceinline__ void cpa16(uint32_t dst, const void* src){
    asm volatile("cp.async.cg.shared.global [%0], [%1], 16;" :: "r"(dst), "l"(src));
}
#define CP_COMMIT() asm volatile("cp.async.commit_group;")
#define CP_WAIT(N)  asm volatile("cp.async.wait_group %0;" :: "n"(N))

__device__ __forceinline__ uint32_t sw64(uint32_t tile, int r, int c16){
    return tile + (uint32_t)r*64u + (uint32_t)((c16 ^ ((r>>1)&3))<<4);
}
__device__ __forceinline__ uint32_t sw128(uint32_t tile, int r, int c16){
    return tile + (uint32_t)r*128u + (uint32_t)((c16 ^ (r&7))<<4);
}

// ---------------------------------------------------------------------------
// Kernel 0: convert X + 6 weight matrices fp32 -> bf16 (grid-split)
// ---------------------------------------------------------------------------
#define XBLKS ((2*(size_t)Bb*Cc*Nn/8)/256)    // 4608
#define WBLKS ((6*Cc*Cc/8)/256)               // 192

__global__ void __launch_bounds__(256) k_cvtall(
    const float* __restrict__ xr, const float* __restrict__ xi,
    const float* __restrict__ qwr, const float* __restrict__ qwi,
    const float* __restrict__ kwr, const float* __restrict__ kwi,
    const float* __restrict__ vwr, const float* __restrict__ vwi)
{
    if (blockIdx.x < XBLKS) {
        const size_t i8 = ((size_t)blockIdx.x*256 + threadIdx.x) * 8;
        const size_t half = (size_t)Bb*Cc*Nn;
        const int p = (i8 >= half) ? 1 : 0;
        const size_t rem = i8 - (size_t)p*half;
        const float* x = p ? xi : xr;
        float4 a = *(const float4*)(x + rem);
        float4 b = *(const float4*)(x + rem + 4);
        uint4 o;
        o.x = packbf(a.x,a.y); o.y = packbf(a.z,a.w);
        o.z = packbf(b.x,b.y); o.w = packbf(b.z,b.w);
        *(uint4*)(g_xb[p] + rem) = o;
    } else {
        const float* mats[6] = { qwr, qwi, kwr, kwi, vwr, vwi };
        const int i8 = ((blockIdx.x - (int)XBLKS)*256 + threadIdx.x) * 8;
        const int mat = i8 >> 16;
        const int rem = i8 & 65535;
        const float* src = mats[mat];
        float4 a = *(const float4*)(src + rem);
        float4 b = *(const float4*)(src + rem + 4);
        uint4 o;
        o.x = packbf(a.x,a.y); o.y = packbf(a.z,a.w);
        o.z = packbf(b.x,b.y); o.w = packbf(b.z,b.w);
        *(uint4*)(g_wb[mat] + rem) = o;
    }
}

// ---------------------------------------------------------------------------
// Kernel 1: complex projection, cp.async 3-stage ring, K-step 32.
// ---------------------------------------------------------------------------
#define PJ_XPART 8704
#define PJ_WOFF  17408
#define PJ_WPART 4096
#define PJ_STAGE 25600
#define PJ_SMEM  (3*PJ_STAGE)

__global__ void __launch_bounds__(256) k_proj(
    const float* __restrict__ qbr, const float* __restrict__ qbi,
    const float* __restrict__ kbr, const float* __restrict__ kbi,
    const float* __restrict__ vbr, const float* __restrict__ vbi)
{
    extern __shared__ __align__(16) unsigned char dyn[];
    const uint32_t base = s2u(dyn);

    const int wsel = blockIdx.z;
    const float* brv = (wsel==0)?qbr:(wsel==1)?kbr:vbr;
    const float* biv = (wsel==0)?qbi:(wsel==1)?kbi:vbi;
    __nv_bfloat16* yr = (wsel==0)?g_q[0]:(wsel==1)?g_k[0]:g_v[0];
    __nv_bfloat16* yi = (wsel==0)?g_q[1]:(wsel==1)?g_k[1]:g_v[1];

    const int tid = threadIdx.x;
    const int w = tid >> 5, lane = tid & 31;
    const int gr = lane >> 2, tg = lane & 3;
    const int wm = w & 3, wn = w >> 2;
    const int m0 = blockIdx.x * 128;
    const int d0 = blockIdx.y * 64;
    const int b  = m0 / Nn;
    const int n0 = m0 - b*Nn;

    const __nv_bfloat16* xbp[2] = { g_xb[0] + (size_t)b*Cc*Nn, g_xb[1] + (size_t)b*Cc*Nn };
    const __nv_bfloat16* wbp[2] = { g_wb[wsel*2], g_wb[wsel*2+1] };

    float accr[2][4][4], acci[2][4][4];
    #pragma unroll
    for (int mf=0; mf<2; ++mf)
        #pragma unroll
        for (int nf=0; nf<4; ++nf)
            #pragma unroll
            for (int e=0; e<4; ++e){ accr[mf][nf][e]=0.f; acci[mf][nf][e]=0.f; }

    auto load_stage = [&](int s, int ck){
        const uint32_t st = base + s*PJ_STAGE;
        #pragma unroll
        for (int it=0; it<4; ++it){
            int idx = tid + 256*it;
            int p = idx>>9, r = (idx>>4)&31, c = idx&15;
            cpa16(st + p*PJ_XPART + r*272 + c*16,
                  xbp[p] + (size_t)(ck+r)*Nn + n0 + c*8);
        }
        #pragma unroll
        for (int it=0; it<2; ++it){
            int idx = tid + 256*it;
            int p = idx>>8, r = (idx>>2)&63, c = idx&3;
            cpa16(sw64(st + PJ_WOFF + p*PJ_WPART, r, c),
                  wbp[p] + (size_t)(d0+r)*Cc + ck + c*8);
        }
        CP_COMMIT();
    };

    load_stage(0, 0);
    load_stage(1, 32);

    for (int kt = 0; kt < 8; ++kt) {
        const int s = kt % 3;
        if (kt < 7) { CP_WAIT(1); } else { CP_WAIT(0); }
        __syncthreads();
        if (kt + 2 < 8) load_stage((kt+2)%3, (kt+2)*32);

        const uint32_t st = base + s*PJ_STAGE;
        #pragma unroll
        for (int ks=0; ks<32; ks+=16) {
            uint32_t axr[2][4], axi[2][4], ain[2][4];
            #pragma unroll
            for (int mf=0; mf<2; ++mf) {
                int crow = ks + (lane&7) + (lane>>4)*8;
                int mcol = wm*32 + mf*16 + ((lane>>3)&1)*8;
                ldsm4t(axr[mf], st + 0*PJ_XPART + (uint32_t)crow*272 + (uint32_t)mcol*2);
                ldsm4t(axi[mf], st + 1*PJ_XPART + (uint32_t)crow*272 + (uint32_t)mcol*2);
                #pragma unroll
                for (int e=0;e<4;++e) ain[mf][e] = axi[mf][e] ^ 0x80008000u;
            }
            #pragma unroll
            for (int nf2=0; nf2<2; ++nf2) {
                int rr = wn*32 + nf2*16 + (lane>>4)*8 + (lane&7);
                int c16 = (ks>>3) + ((lane>>3)&1);
                uint32_t bwr[4], bwi[4];
                ldsm4(bwr, sw64(st + PJ_WOFF,            rr, c16));
                ldsm4(bwi, sw64(st + PJ_WOFF + PJ_WPART, rr, c16));
                #pragma unroll
                for (int h=0; h<2; ++h) {
                    int nfr = nf2*2 + h;
                    #pragma unroll
                    for (int mf=0; mf<2; ++mf) {
                        mma16(accr[mf][nfr], axr[mf], bwr + 2*h);
                        mma16(accr[mf][nfr], ain[mf], bwi + 2*h);
                        mma16(acci[mf][nfr], axr[mf], bwi + 2*h);
                        mma16(acci[mf][nfr], axi[mf], bwr + 2*h);
                    }
                }
            }
        }
        __syncthreads();
    }

    #pragma unroll
    for (int mf=0; mf<2; ++mf) {
        const int row0 = m0 + wm*32 + mf*16 + gr;
        #pragma unroll
        for (int nfr=0; nfr<4; ++nfr) {
            const int col0 = d0 + wn*32 + nfr*8 + 2*tg;
            const float b0r = brv[col0], b1r = brv[col0+1];
            const float b0i = biv[col0], b1i = biv[col0+1];
            *(uint32_t*)&yr[(size_t)row0*Cc + col0]     = packbf(accr[mf][nfr][0]+b0r, accr[mf][nfr][1]+b1r);
            *(uint32_t*)&yr[(size_t)(row0+8)*Cc + col0] = packbf(accr[mf][nfr][2]+b0r, accr[mf][nfr][3]+b1r);
            *(uint32_t*)&yi[(size_t)row0*Cc + col0]     = packbf(acci[mf][nfr][0]+b0i, acci[mf][nfr][1]+b1i);
            *(uint32_t*)&yi[(size_t)(row0+8)*Cc + col0] = packbf(acci[mf][nfr][2]+b0i, acci[mf][nfr][3]+b1i);
        }
    }
}

// ---------------------------------------------------------------------------
// Kernel 2: scores + exp. Block 128n x 128m, warps 2(n)x4(m), warp 64x32.
// ---------------------------------------------------------------------------
#define SC_STAGE 32768
#define SC_SMEM  (3*SC_STAGE)

__global__ void __launch_bounds__(256) k_scores()
{
    extern __shared__ __align__(16) unsigned char dyn[];
    const uint32_t base = s2u(dyn);

    const int tid = threadIdx.x;
    const int w = tid >> 5, lane = tid & 31;
    const int gr = lane >> 2, tg = lane & 3;
    const int wrow = w & 1, wcol = w >> 1;
    const int m0 = blockIdx.x * 128;
    const int n0 = blockIdx.y * 128;
    const int b  = blockIdx.z;

    const __nv_bfloat16* srcs[4] = {
        g_q[0] + (size_t)b*Nn*Cc, g_q[1] + (size_t)b*Nn*Cc,
        g_k[0] + (size_t)b*Nn*Cc, g_k[1] + (size_t)b*Nn*Cc };
    const int rbase[4] = { n0, n0, m0, m0 };

    float acc[4][4][4];
    #pragma unroll
    for (int mf=0; mf<4; ++mf)
        #pragma unroll
        for (int nf=0; nf<4; ++nf)
            #pragma unroll
            for (int e=0; e<4; ++e) acc[mf][nf][e]=0.f;

    auto load_stage = [&](int s, int ck){
        const uint32_t st = base + s*SC_STAGE;
        #pragma unroll
        for (int t=0;t<4;++t){
            const uint32_t tb = st + t*8192;
            #pragma unroll
            for (int it=0; it<2; ++it){
                int idx = tid + 256*it;
                int r = idx>>2, c = idx&3;
                cpa16(sw64(tb, r, c), srcs[t] + (size_t)(rbase[t]+r)*Cc + ck + c*8);
            }
        }
        CP_COMMIT();
    };

    load_stage(0, 0);
    load_stage(1, 32);

    for (int kt = 0; kt < 8; ++kt) {
        const int s = kt % 3;
        if (kt < 7) { CP_WAIT(1); } else { CP_WAIT(0); }
        __syncthreads();
        if (kt + 2 < 8) load_stage((kt+2)%3, (kt+2)*32);

        const uint32_t st = base + s*SC_STAGE;
        #pragma unroll
        for (int p=0; p<2; ++p) {
            const uint32_t qt = st + p*8192;
            const uint32_t ktile = st + 16384 + p*8192;
            #pragma unroll
            for (int ks=0; ks<32; ks+=16) {
                uint32_t a[4][4];
                #pragma unroll
                for (int mf=0; mf<4; ++mf) {
                    int r = wrow*64 + mf*16 + (lane&15);
                    int c16 = (ks>>3) + (lane>>4);
                    ldsm4(a[mf], sw64(qt, r, c16));
                }
                #pragma unroll
                for (int nf2=0; nf2<2; ++nf2) {
                    int rr = wcol*32 + nf2*16 + (lane>>4)*8 + (lane&7);
                    int c16 = (ks>>3) + ((lane>>3)&1);
                    uint32_t bb[4];
                    ldsm4(bb, sw64(ktile, rr, c16));
                    #pragma unroll
                    for (int mf=0; mf<4; ++mf) {
                        mma16(acc[mf][nf2*2  ], a[mf], bb);
                        mma16(acc[mf][nf2*2+1], a[mf], bb+2);
                    }
                }
            }
        }
        __syncthreads();
    }

    // epilogue: exp + store + deterministic partial row sums
    float (*spsum)[128] = (float(*)[128])dyn;
    const float sc = 1.0f/16.0f;
    #pragma unroll
    for (int mf=0; mf<4; ++mf) {
        const int row0 = n0 + wrow*64 + mf*16 + gr;
        const size_t r0b = (size_t)b*Nn*Nn + (size_t)row0*Nn;
        const size_t r1b = r0b + (size_t)8*Nn;
        float p0 = 0.f, p1 = 0.f;
        #pragma unroll
        for (int nfr=0; nfr<4; ++nfr) {
            const int col0 = m0 + wcol*32 + nfr*8 + 2*tg;
            float e0 = __expf(acc[mf][nfr][0]*sc);
            float e1 = __expf(acc[mf][nfr][1]*sc);
            float e2 = __expf(acc[mf][nfr][2]*sc);
            float e3 = __expf(acc[mf][nfr][3]*sc);
            *(uint32_t*)&g_attnb[r0b + col0] = packbf(e0, e1);
            *(uint32_t*)&g_attnb[r1b + col0] = packbf(e2, e3);
            p0 += e0 + e1;
            p1 += e2 + e3;
        }
        p0 += __shfl_xor_sync(0xFFFFFFFFu, p0, 1);
        p0 += __shfl_xor_sync(0xFFFFFFFFu, p0, 2);
        p1 += __shfl_xor_sync(0xFFFFFFFFu, p1, 1);
        p1 += __shfl_xor_sync(0xFFFFFFFFu, p1, 2);
        if (tg == 0) {
            spsum[wcol][wrow*64 + mf*16 + gr    ] = p0;
            spsum[wcol][wrow*64 + mf*16 + gr + 8] = p1;
        }
    }
    __syncthreads();
    if (tid < 128) {
        float s4 = spsum[0][tid] + spsum[1][tid] + spsum[2][tid] + spsum[3][tid];
        g_psum[((size_t)b*NMB + (m0>>7))*Nn + n0 + tid] = s4;
    }
}

// ---------------------------------------------------------------------------
// Kernel 3: row-sum reduce -> 1/sum
// ---------------------------------------------------------------------------
__global__ void __launch_bounds__(256) k_rowsum()
{
    const int i = blockIdx.x*256 + threadIdx.x;
    const int b = i / Nn, n = i - b*Nn;
    float s = 0.f;
    #pragma unroll
    for (int mb=0; mb<NMB; ++mb)
        s += g_psum[((size_t)b*NMB + mb)*Nn + n];
    g_rinv[i] = 1.f / s;
}

// ---------------------------------------------------------------------------
// Kernel 4: AV + fused BN partial stats (coalesced). 3-stage, K-step 64.
// ---------------------------------------------------------------------------
#define AV_VOFF  16384
#define AV_STAGE (16384 + 18432)   // 34816
#define AV_SMEM  (3*AV_STAGE)      // 104448

__global__ void __launch_bounds__(256) k_av(
    const float* __restrict__ xr, const float* __restrict__ xi,
    const float* __restrict__ gamma)
{
    extern __shared__ __align__(16) unsigned char dyn[];
    const uint32_t base = s2u(dyn);

    const int tid = threadIdx.x;
    const int w = tid >> 5, lane = tid & 31;
    const int gr = lane >> 2, tg = lane & 3;
    const int wm = w & 3, wn = w >> 2;
    const int n0 = blockIdx.x * 128;
    const int d0 = blockIdx.y * 64;
    const int b  = blockIdx.z;

    const __nv_bfloat16* Ab  = g_attnb + (size_t)b*Nn*Nn;
    const __nv_bfloat16* vp[2] = { g_v[0] + (size_t)b*Nn*Cc, g_v[1] + (size_t)b*Nn*Cc };

    float accr[2][4][4], acci[2][4][4];
    #pragma unroll
    for (int mf=0; mf<2; ++mf)
        #pragma unroll
        for (int nf=0; nf<4; ++nf)
            #pragma unroll
            for (int e=0; e<4; ++e){ accr[mf][nf][e]=0.f; acci[mf][nf][e]=0.f; }

    auto load_stage = [&](int s, int mk){
        const uint32_t st = base + s*AV_STAGE;
        #pragma unroll
        for (int it=0; it<4; ++it){
            int idx = tid + 256*it;
            int r = idx>>3, c = idx&7;
            cpa16(sw128(st, r, c), Ab + (size_t)(n0+r)*Nn + mk + c*8);
        }
        #pragma unroll
        for (int it=0; it<4; ++it){
            int idx = tid + 256*it;
            int p = idx>>9, r = (idx>>3)&63, c = idx&7;
            cpa16(st + AV_VOFF + p*9216 + r*144 + c*16,
                  vp[p] + (size_t)(mk+r)*Cc + d0 + c*8);
        }
        CP_COMMIT();
    };

    load_stage(0, 0);
    load_stage(1, 64);

    const int NKT = Nn/64;   // 36
    for (int kt = 0; kt < NKT; ++kt) {
        const int s = kt % 3;
        if (kt < NKT-1) { CP_WAIT(1); } else { CP_WAIT(0); }
        __syncthreads();
        if (kt + 2 < NKT) load_stage((kt+2)%3, (kt+2)*64);

        const uint32_t st = base + s*AV_STAGE;
        #pragma unroll
        for (int ks=0; ks<64; ks+=16) {
            uint32_t a[2][4];
            #pragma unroll
            for (int mf=0; mf<2; ++mf) {
                int r = wm*32 + mf*16 + (lane&15);
                int c16 = (ks>>3) + (lane>>4);
                ldsm4(a[mf], sw128(st, r, c16));
            }
            #pragma unroll
            for (int nf2=0; nf2<2; ++nf2) {
                int cb = wn*32 + nf2*16;
                uint32_t bvr[4], bvi[4];
                uint32_t vaddr = st + AV_VOFF + (uint32_t)(ks + (lane&15))*144 + (uint32_t)(cb + (lane>>4)*8)*2;
                ldsm4t(bvr, vaddr);
                ldsm4t(bvi, vaddr + 9216);
                #pragma unroll
                for (int h=0; h<2; ++h) {
                    int nfr = nf2*2 + h;
                    #pragma unroll
                    for (int mf=0; mf<2; ++mf) {
                        mma16(accr[mf][nfr], a[mf], bvr + 2*h);
                        mma16(acci[mf][nfr], a[mf], bvi + 2*h);
                    }
                }
            }
        }
        __syncthreads();
    }

    float rin[2][2];
    #pragma unroll
    for (int mf=0; mf<2; ++mf) {
        rin[mf][0] = g_rinv[(size_t)b*Nn + n0 + wm*32 + mf*16 + gr];
        rin[mf][1] = g_rinv[(size_t)b*Nn + n0 + wm*32 + mf*16 + gr + 8];
    }
    const float gma = gamma[0];

    // transpose epilogue -> g_outT [d][n] bf16 + coalesced fused BN stats
    __nv_bfloat16 (*stage)[144] = (__nv_bfloat16(*)[144])dyn;
    const size_t basep = (size_t)b*Cc*Nn + (size_t)d0*Nn + n0;
    const int wi = b*NMB + blockIdx.x;   // partial index 0..143
    #pragma unroll
    for (int p=0; p<2; ++p) {
        __syncthreads();
        #pragma unroll
        for (int mf=0; mf<2; ++mf) {
            int rl = wm*32 + mf*16 + gr;
            #pragma unroll
            for (int nfr=0; nfr<4; ++nfr) {
                int cl = wn*32 + nfr*8 + 2*tg;
                float* acc = p ? acci[mf][nfr] : accr[mf][nfr];
                stage[cl  ][rl  ] = __float2bfloat16(acc[0]*rin[mf][0]);
                stage[cl+1][rl  ] = __float2bfloat16(acc[1]*rin[mf][0]);
                stage[cl  ][rl+8] = __float2bfloat16(acc[2]*rin[mf][1]);
                stage[cl+1][rl+8] = __float2bfloat16(acc[3]*rin[mf][1]);
            }
        }
        __syncthreads();
        #pragma unroll
        for (int it=0; it<4; ++it) {
            int idx = tid + 256*it;
            int dl = idx >> 4, c8 = idx & 15;
            *(uint4*)(g_outT[p] + basep + (size_t)dl*Nn + c8*8) = *(const uint4*)&stage[dl][c8*8];
        }
        // coalesced fused BN partial stats: z = x + gamma*out(bf16)
        {
            const float* x = p ? xi : xr;
            #pragma unroll
            for (int it=0; it<4; ++it) {
                const int dl = (tid >> 4) + it*16;    // row 0..63
                const int c8 = tid & 15;              // 8-elem chunk
                const float* xp = x + (size_t)b*Cc*Nn + (size_t)(d0+dl)*Nn + n0 + c8*8;
                float4 xv0 = *(const float4*)xp;
                float4 xv1 = *(const float4*)(xp + 4);
                const __nv_bfloat16* sp = &stage[dl][c8*8];
                float xs[8] = {xv0.x,xv0.y,xv0.z,xv0.w,xv1.x,xv1.y,xv1.z,xv1.w};
                float s = 0.f, ss = 0.f;
                #pragma unroll
                for (int j=0;j<8;++j){
                    float z = xs[j] + gma*__bfloat162float(sp[j]);
                    s += z; ss += z*z;
                }
                #pragma unroll
                for (int off=1; off<16; off<<=1){
                    s  += __shfl_xor_sync(0xFFFFFFFFu, s,  off);
                    ss += __shfl_xor_sync(0xFFFFFFFFu, ss, off);
                }
                if ((tid & 15) == 0) {
                    g_bnps[p][d0+dl][wi][0] = s;
                    g_bnps[p][d0+dl][wi][1] = ss;
                }
            }
        }
    }
}

// ---------------------------------------------------------------------------
// Kernel 5: BN stats reduce (144 partials per channel) -> mean, rstd
// ---------------------------------------------------------------------------
__global__ void __launch_bounds__(256) k_bnred()
{
    const int c = blockIdx.x, p = blockIdx.y;
    const int tid = threadIdx.x;
    float s = 0.f, ss = 0.f;
    if (tid < Bb*NMB) {
        s  = g_bnps[p][c][tid][0];
        ss = g_bnps[p][c][tid][1];
    }
    __shared__ float rs[256], rss[256];
    rs[tid] = s; rss[tid] = ss; __syncthreads();
    #pragma unroll
    for (int st = 128; st > 0; st >>= 1) {
        if (tid < st) { rs[tid] += rs[tid+st]; rss[tid] += rss[tid+st]; }
        __syncthreads();
    }
    if (tid == 0) {
        const float inv_cnt = 1.f / (float)Mtot;
        float mean = rs[0] * inv_cnt;
        float var  = rss[0] * inv_cnt - mean*mean;
        g_mean[p][c] = mean;
        g_rstd[p][c] = rsqrtf(var + EPSf);
    }
}

// ---------------------------------------------------------------------------
// Kernel 6: BN apply
// ---------------------------------------------------------------------------
__global__ void __launch_bounds__(256) k_bnapply(
    const float* __restrict__ xr, const float* __restrict__ xi,
    const float* __restrict__ gamma,
    const float* __restrict__ bnwr, const float* __restrict__ bnbr,
    const float* __restrict__ bnwi, const float* __restrict__ bnbi,
    float* __restrict__ out)
{
    const int idx4 = blockIdx.x*256 + threadIdx.x;
    const size_t e = (size_t)idx4 * 4;
    const size_t half = (size_t)Bb*Cc*Nn;
    const int p = (e >= half) ? 1 : 0;
    const size_t rem = e - (size_t)p*half;
    const int c = (int)((rem / Nn) % Cc);

    const float* x = p ? xi : xr;
    const float g = gamma[0];
    const float wsc = (p ? bnwi[c] : bnwr[c]) * g_rstd[p][c];
    const float bia = (p ? bnbi[c] : bnbr[c]);
    const float mu = g_mean[p][c];

    float4 xv = *(const float4*)(x + rem);
    uint2 ou = *(const uint2*)(g_outT[p] + rem);
    float2 o01 = __bfloat1622float2(*reinterpret_cast<const __nv_bfloat162*>(&ou.x));
    float2 o23 = __bfloat1622float2(*reinterpret_cast<const __nv_bfloat162*>(&ou.y));

    float4 r;
    r.x = (xv.x + g*o01.x - mu) * wsc + bia;
    r.y = (xv.y + g*o01.y - mu) * wsc + bia;
    r.z = (xv.z + g*o23.x - mu) * wsc + bia;
    r.w = (xv.w + g*o23.y - mu) * wsc + bia;
    *(float4*)(out + e) = r;
}

// ---------------------------------------------------------------------------
// Launch
// ---------------------------------------------------------------------------
extern "C" void kernel_launch(void* const* d_in, const int* in_sizes, int n_in,
                              void* d_out, int out_size)
{
    const float* xr   = (const float*)d_in[0];
    const float* xi   = (const float*)d_in[1];
    const float* q_wr = (const float*)d_in[2];
    const float* q_wi = (const float*)d_in[3];
    const float* q_br = (const float*)d_in[4];
    const float* q_bi = (const float*)d_in[5];
    const float* k_wr = (const float*)d_in[6];
    const float* k_wi = (const float*)d_in[7];
    const float* k_br = (const float*)d_in[8];
    const float* k_bi = (const float*)d_in[9];
    const float* v_wr = (const float*)d_in[10];
    const float* v_wi = (const float*)d_in[11];
    const float* v_br = (const float*)d_in[12];
    const float* v_bi = (const float*)d_in[13];
    const float* gamma= (const float*)d_in[14];
    const float* bnwr = (const float*)d_in[15];
    const float* bnbr = (const float*)d_in[16];
    const float* bnwi = (const float*)d_in[17];
    const float* bnbi = (const float*)d_in[18];
    float* out = (float*)d_out;

    cudaFuncSetAttribute(k_proj,   cudaFuncAttributeMaxDynamicSharedMemorySize, PJ_SMEM);
    cudaFuncSetAttribute(k_scores, cudaFuncAttributeMaxDynamicSharedMemorySize, SC_SMEM);
    cudaFuncSetAttribute(k_av,     cudaFuncAttributeMaxDynamicSharedMemorySize, AV_SMEM);

    k_cvtall<<<(unsigned)(XBLKS + WBLKS), 256>>>(xr, xi, q_wr, q_wi, k_wr, k_wi, v_wr, v_wi);

    k_proj<<<dim3(Mtot/128, Cc/64, 3), 256, PJ_SMEM>>>(q_br, q_bi, k_br, k_bi, v_br, v_bi);

    k_scores<<<dim3(Nn/128, Nn/128, Bb), 256, SC_SMEM>>>();
    k_rowsum<<<Mtot/256, 256>>>();
    k_av<<<dim3(Nn/128, Cc/64, Bb), 256, AV_SMEM>>>(xr, xi, gamma);

    k_bnred<<<dim3(Cc, 2), 256>>>();
    k_bnapply<<<(2*(size_t)Bb*Cc*Nn/4)/256, 256>>>(xr, xi, gamma, bnwr, bnbr, bnwi, bnbi, out);
}

// round 14
// speedup vs baseline: 1.1687x; 1.0540x over previous
#include <cuda_runtime.h>
#include <cuda_bf16.h>
#include <math.h>
#include <stdint.h>

#define Bb   8
#define Cc   256
#define Nn   2304
#define Mtot (Bb*Nn)
#define NMB  (Nn/128)      // 18 n-blocks
#define EPSf 1e-5f

// ---------------------------------------------------------------------------
// Scratch
// ---------------------------------------------------------------------------
__device__ __align__(128) __nv_bfloat16 g_xb[2][(size_t)Bb*Cc*Nn];   // bf16 X [p][b][c][n]
__device__ __align__(128) __nv_bfloat16 g_wb[6][(size_t)Cc*Cc];      // bf16 W
__device__ __align__(128) __nv_bfloat16 g_q[2][(size_t)Mtot*Cc];
__device__ __align__(128) __nv_bfloat16 g_k[2][(size_t)Mtot*Cc];
__device__ __align__(128) __nv_bfloat16 g_v[2][(size_t)Mtot*Cc];
__device__ __align__(128) __nv_bfloat16 g_attnb[(size_t)Bb*Nn*Nn];   // bf16 exp(S)
__device__ __align__(128) float g_psum[(size_t)Bb*NMB*Nn];           // partial row sums
__device__ __align__(128) __nv_bfloat16 g_outT[2][(size_t)Bb*Cc*Nn]; // bf16 [p][b][c][n]
__device__ __align__(128) float g_bnps[2][Cc][Bb*NMB][2];            // per-(c, part) (sum, sumsq)
__device__ float g_mean[2][Cc];
__device__ float g_rstd[2][Cc];

// ---------------------------------------------------------------------------
// helpers
// ---------------------------------------------------------------------------
__device__ __forceinline__ uint32_t s2u(const void* p){
    return (uint32_t)__cvta_generic_to_shared(p);
}
__device__ __forceinline__ uint32_t packbf(float lo, float hi){
    uint32_t r;
    asm("cvt.rn.bf16x2.f32 %0, %1, %2;" : "=r"(r) : "f"(hi), "f"(lo));
    return r;
}
__device__ __forceinline__ void mma16(float* d, const uint32_t* a, const uint32_t* b){
    asm volatile("mma.sync.aligned.m16n8k16.row.col.f32.bf16.bf16.f32 "
        "{%0,%1,%2,%3}, {%4,%5,%6,%7}, {%8,%9}, {%0,%1,%2,%3};"
        : "+f"(d[0]),"+f"(d[1]),"+f"(d[2]),"+f"(d[3])
        : "r"(a[0]),"r"(a[1]),"r"(a[2]),"r"(a[3]),"r"(b[0]),"r"(b[1]));
}
__device__ __forceinline__ void ldsm4(uint32_t* r, uint32_t addr){
    asm volatile("ldmatrix.sync.aligned.m8n8.x4.shared.b16 {%0,%1,%2,%3}, [%4];"
        : "=r"(r[0]),"=r"(r[1]),"=r"(r[2]),"=r"(r[3]) : "r"(addr));
}
__device__ __forceinline__ void ldsm4t(uint32_t* r, uint32_t addr){
    asm volatile("ldmatrix.sync.aligned.m8n8.x4.trans.shared.b16 {%0,%1,%2,%3}, [%4];"
        : "=r"(r[0]),"=r"(r[1]),"=r"(r[2]),"=r"(r[3]) : "r"(addr));
}
__device__ __forceinline__ void cpa16(uint32_t dst, const void* src){
    asm volatile("cp.async.cg.shared.global [%0], [%1], 16;" :: "r"(dst), "l"(src));
}
#define CP_COMMIT() asm volatile("cp.async.commit_group;")
#define CP_WAIT(N)  asm volatile("cp.async.wait_group %0;" :: "n"(N))

__device__ __forceinline__ uint32_t sw64(uint32_t tile, int r, int c16){
    return tile + (uint32_t)r*64u + (uint32_t)((c16 ^ ((r>>1)&3))<<4);
}
__device__ __forceinline__ uint32_t sw128(uint32_t tile, int r, int c16){
    return tile + (uint32_t)r*128u + (uint32_t)((c16 ^ (r&7))<<4);
}

// ---------------------------------------------------------------------------
// Kernel 0: convert X + 6 weight matrices fp32 -> bf16 (grid-split)
// ---------------------------------------------------------------------------
#define XBLKS ((2*(size_t)Bb*Cc*Nn/8)/256)    // 4608
#define WBLKS ((6*Cc*Cc/8)/256)               // 192

__global__ void __launch_bounds__(256) k_cvtall(
    const float* __restrict__ xr, const float* __restrict__ xi,
    const float* __restrict__ qwr, const float* __restrict__ qwi,
    const float* __restrict__ kwr, const float* __restrict__ kwi,
    const float* __restrict__ vwr, const float* __restrict__ vwi)
{
    if (blockIdx.x < XBLKS) {
        const size_t i8 = ((size_t)blockIdx.x*256 + threadIdx.x) * 8;
        const size_t half = (size_t)Bb*Cc*Nn;
        const int p = (i8 >= half) ? 1 : 0;
        const size_t rem = i8 - (size_t)p*half;
        const float* x = p ? xi : xr;
        float4 a = *(const float4*)(x + rem);
        float4 b = *(const float4*)(x + rem + 4);
        uint4 o;
        o.x = packbf(a.x,a.y); o.y = packbf(a.z,a.w);
        o.z = packbf(b.x,b.y); o.w = packbf(b.z,b.w);
        *(uint4*)(g_xb[p] + rem) = o;
    } else {
        const float* mats[6] = { qwr, qwi, kwr, kwi, vwr, vwi };
        const int i8 = ((blockIdx.x - (int)XBLKS)*256 + threadIdx.x) * 8;
        const int mat = i8 >> 16;
        const int rem = i8 & 65535;
        const float* src = mats[mat];
        float4 a = *(const float4*)(src + rem);
        float4 b = *(const float4*)(src + rem + 4);
        uint4 o;
        o.x = packbf(a.x,a.y); o.y = packbf(a.z,a.w);
        o.z = packbf(b.x,b.y); o.w = packbf(b.z,b.w);
        *(uint4*)(g_wb[mat] + rem) = o;
    }
}

// ---------------------------------------------------------------------------
// Kernel 1: complex projection, cp.async 3-stage ring, K-step 32.
//   Epilogue staged through smem for coalesced 16B stores.
// ---------------------------------------------------------------------------
#define PJ_XPART 8704
#define PJ_WOFF  17408
#define PJ_WPART 4096
#define PJ_STAGE 25600
#define PJ_SMEM  (3*PJ_STAGE)

__global__ void __launch_bounds__(256) k_proj(
    const float* __restrict__ qbr, const float* __restrict__ qbi,
    const float* __restrict__ kbr, const float* __restrict__ kbi,
    const float* __restrict__ vbr, const float* __restrict__ vbi)
{
    extern __shared__ __align__(16) unsigned char dyn[];
    const uint32_t base = s2u(dyn);

    const int wsel = blockIdx.z;
    const float* brv = (wsel==0)?qbr:(wsel==1)?kbr:vbr;
    const float* biv = (wsel==0)?qbi:(wsel==1)?kbi:vbi;
    __nv_bfloat16* yr = (wsel==0)?g_q[0]:(wsel==1)?g_k[0]:g_v[0];
    __nv_bfloat16* yi = (wsel==0)?g_q[1]:(wsel==1)?g_k[1]:g_v[1];

    const int tid = threadIdx.x;
    const int w = tid >> 5, lane = tid & 31;
    const int gr = lane >> 2, tg = lane & 3;
    const int wm = w & 3, wn = w >> 2;
    const int m0 = blockIdx.x * 128;
    const int d0 = blockIdx.y * 64;
    const int b  = m0 / Nn;
    const int n0 = m0 - b*Nn;

    const __nv_bfloat16* xbp[2] = { g_xb[0] + (size_t)b*Cc*Nn, g_xb[1] + (size_t)b*Cc*Nn };
    const __nv_bfloat16* wbp[2] = { g_wb[wsel*2], g_wb[wsel*2+1] };

    float accr[2][4][4], acci[2][4][4];
    #pragma unroll
    for (int mf=0; mf<2; ++mf)
        #pragma unroll
        for (int nf=0; nf<4; ++nf)
            #pragma unroll
            for (int e=0; e<4; ++e){ accr[mf][nf][e]=0.f; acci[mf][nf][e]=0.f; }

    auto load_stage = [&](int s, int ck){
        const uint32_t st = base + s*PJ_STAGE;
        #pragma unroll
        for (int it=0; it<4; ++it){
            int idx = tid + 256*it;
            int p = idx>>9, r = (idx>>4)&31, c = idx&15;
            cpa16(st + p*PJ_XPART + r*272 + c*16,
                  xbp[p] + (size_t)(ck+r)*Nn + n0 + c*8);
        }
        #pragma unroll
        for (int it=0; it<2; ++it){
            int idx = tid + 256*it;
            int p = idx>>8, r = (idx>>2)&63, c = idx&3;
            cpa16(sw64(st + PJ_WOFF + p*PJ_WPART, r, c),
                  wbp[p] + (size_t)(d0+r)*Cc + ck + c*8);
        }
        CP_COMMIT();
    };

    load_stage(0, 0);
    load_stage(1, 32);

    for (int kt = 0; kt < 8; ++kt) {
        const int s = kt % 3;
        if (kt < 7) { CP_WAIT(1); } else { CP_WAIT(0); }
        __syncthreads();
        if (kt + 2 < 8) load_stage((kt+2)%3, (kt+2)*32);

        const uint32_t st = base + s*PJ_STAGE;
        #pragma unroll
        for (int ks=0; ks<32; ks+=16) {
            uint32_t axr[2][4], axi[2][4], ain[2][4];
            #pragma unroll
            for (int mf=0; mf<2; ++mf) {
                int crow = ks + (lane&7) + (lane>>4)*8;
                int mcol = wm*32 + mf*16 + ((lane>>3)&1)*8;
                ldsm4t(axr[mf], st + 0*PJ_XPART + (uint32_t)crow*272 + (uint32_t)mcol*2);
                ldsm4t(axi[mf], st + 1*PJ_XPART + (uint32_t)crow*272 + (uint32_t)mcol*2);
                #pragma unroll
                for (int e=0;e<4;++e) ain[mf][e] = axi[mf][e] ^ 0x80008000u;
            }
            #pragma unroll
            for (int nf2=0; nf2<2; ++nf2) {
                int rr = wn*32 + nf2*16 + (lane>>4)*8 + (lane&7);
                int c16 = (ks>>3) + ((lane>>3)&1);
                uint32_t bwr[4], bwi[4];
                ldsm4(bwr, sw64(st + PJ_WOFF,            rr, c16));
                ldsm4(bwi, sw64(st + PJ_WOFF + PJ_WPART, rr, c16));
                #pragma unroll
                for (int h=0; h<2; ++h) {
                    int nfr = nf2*2 + h;
                    #pragma unroll
                    for (int mf=0; mf<2; ++mf) {
                        mma16(accr[mf][nfr], axr[mf], bwr + 2*h);
                        mma16(accr[mf][nfr], ain[mf], bwi + 2*h);
                        mma16(acci[mf][nfr], axr[mf], bwi + 2*h);
                        mma16(acci[mf][nfr], axi[mf], bwr + 2*h);
                    }
                }
            }
        }
        __syncthreads();
    }

    // epilogue: stage bf16 [m 128][d 72-pitch], coalesced 16B writes
    __nv_bfloat16 (*pst)[72] = (__nv_bfloat16(*)[72])dyn;   // 18432 B
    #pragma unroll
    for (int p=0; p<2; ++p) {
        __syncthreads();
        __nv_bfloat16* dst = p ? yi : yr;
        #pragma unroll
        for (int mf=0; mf<2; ++mf) {
            const int rl = wm*32 + mf*16 + gr;
            #pragma unroll
            for (int nfr=0; nfr<4; ++nfr) {
                const int cl = wn*32 + nfr*8 + 2*tg;
                const float b0 = p ? biv[d0+cl]   : brv[d0+cl];
                const float b1 = p ? biv[d0+cl+1] : brv[d0+cl+1];
                const float* acc = p ? acci[mf][nfr] : accr[mf][nfr];
                *(uint32_t*)&pst[rl  ][cl] = packbf(acc[0]+b0, acc[1]+b1);
                *(uint32_t*)&pst[rl+8][cl] = packbf(acc[2]+b0, acc[3]+b1);
            }
        }
        __syncthreads();
        #pragma unroll
        for (int it=0; it<4; ++it) {
            int idx = tid + 256*it;            // 1024 over 128 rows x 8 chunks
            int row = idx >> 3, c8 = idx & 7;
            *(uint4*)(dst + (size_t)(m0+row)*Cc + d0 + c8*8) = *(const uint4*)&pst[row][c8*8];
        }
    }
}

// ---------------------------------------------------------------------------
// Kernel 2: scores + exp. Epilogue staged through smem, coalesced stores.
// ---------------------------------------------------------------------------
#define SC_STAGE 32768
#define SC_SMEM  (3*SC_STAGE)

__global__ void __launch_bounds__(256) k_scores()
{
    extern __shared__ __align__(16) unsigned char dyn[];
    const uint32_t base = s2u(dyn);

    const int tid = threadIdx.x;
    const int w = tid >> 5, lane = tid & 31;
    const int gr = lane >> 2, tg = lane & 3;
    const int wrow = w & 1, wcol = w >> 1;
    const int m0 = blockIdx.x * 128;
    const int n0 = blockIdx.y * 128;
    const int b  = blockIdx.z;

    const __nv_bfloat16* srcs[4] = {
        g_q[0] + (size_t)b*Nn*Cc, g_q[1] + (size_t)b*Nn*Cc,
        g_k[0] + (size_t)b*Nn*Cc, g_k[1] + (size_t)b*Nn*Cc };
    const int rbase[4] = { n0, n0, m0, m0 };

    float acc[4][4][4];
    #pragma unroll
    for (int mf=0; mf<4; ++mf)
        #pragma unroll
        for (int nf=0; nf<4; ++nf)
            #pragma unroll
            for (int e=0; e<4; ++e) acc[mf][nf][e]=0.f;

    auto load_stage = [&](int s, int ck){
        const uint32_t st = base + s*SC_STAGE;
        #pragma unroll
        for (int t=0;t<4;++t){
            const uint32_t tb = st + t*8192;
            #pragma unroll
            for (int it=0; it<2; ++it){
                int idx = tid + 256*it;
                int r = idx>>2, c = idx&3;
                cpa16(sw64(tb, r, c), srcs[t] + (size_t)(rbase[t]+r)*Cc + ck + c*8);
            }
        }
        CP_COMMIT();
    };

    load_stage(0, 0);
    load_stage(1, 32);

    for (int kt = 0; kt < 8; ++kt) {
        const int s = kt % 3;
        if (kt < 7) { CP_WAIT(1); } else { CP_WAIT(0); }
        __syncthreads();
        if (kt + 2 < 8) load_stage((kt+2)%3, (kt+2)*32);

        const uint32_t st = base + s*SC_STAGE;
        #pragma unroll
        for (int p=0; p<2; ++p) {
            const uint32_t qt = st + p*8192;
            const uint32_t ktile = st + 16384 + p*8192;
            #pragma unroll
            for (int ks=0; ks<32; ks+=16) {
                uint32_t a[4][4];
                #pragma unroll
                for (int mf=0; mf<4; ++mf) {
                    int r = wrow*64 + mf*16 + (lane&15);
                    int c16 = (ks>>3) + (lane>>4);
                    ldsm4(a[mf], sw64(qt, r, c16));
                }
                #pragma unroll
                for (int nf2=0; nf2<2; ++nf2) {
                    int rr = wcol*32 + nf2*16 + (lane>>4)*8 + (lane&7);
                    int c16 = (ks>>3) + ((lane>>3)&1);
                    uint32_t bb[4];
                    ldsm4(bb, sw64(ktile, rr, c16));
                    #pragma unroll
                    for (int mf=0; mf<4; ++mf) {
                        mma16(acc[mf][nf2*2  ], a[mf], bb);
                        mma16(acc[mf][nf2*2+1], a[mf], bb+2);
                    }
                }
            }
        }
        __syncthreads();
    }

    // epilogue: exp -> smem stage; partial row sums; coalesced writes
    __nv_bfloat16 (*sstage)[136] = (__nv_bfloat16(*)[136])dyn;    // 128x136 bf16 = 34816 B
    float (*spsum)[128] = (float(*)[128])(dyn + 36864);           // [4][128] floats
    const float sc = 1.0f/16.0f;
    #pragma unroll
    for (int mf=0; mf<4; ++mf) {
        const int rl = wrow*64 + mf*16 + gr;
        float p0 = 0.f, p1 = 0.f;
        #pragma unroll
        for (int nfr=0; nfr<4; ++nfr) {
            const int cl = wcol*32 + nfr*8 + 2*tg;
            float e0 = __expf(acc[mf][nfr][0]*sc);
            float e1 = __expf(acc[mf][nfr][1]*sc);
            float e2 = __expf(acc[mf][nfr][2]*sc);
            float e3 = __expf(acc[mf][nfr][3]*sc);
            *(uint32_t*)&sstage[rl  ][cl] = packbf(e0, e1);
            *(uint32_t*)&sstage[rl+8][cl] = packbf(e2, e3);
            p0 += e0 + e1;
            p1 += e2 + e3;
        }
        p0 += __shfl_xor_sync(0xFFFFFFFFu, p0, 1);
        p0 += __shfl_xor_sync(0xFFFFFFFFu, p0, 2);
        p1 += __shfl_xor_sync(0xFFFFFFFFu, p1, 1);
        p1 += __shfl_xor_sync(0xFFFFFFFFu, p1, 2);
        if (tg == 0) {
            spsum[wcol][rl    ] = p0;
            spsum[wcol][rl + 8] = p1;
        }
    }
    __syncthreads();
    #pragma unroll
    for (int it=0; it<8; ++it) {
        int idx = tid + 256*it;             // 2048 over 128 rows x 16 chunks
        int row = idx >> 4, c8 = idx & 15;
        *(uint4*)(g_attnb + (size_t)b*Nn*Nn + (size_t)(n0+row)*Nn + m0 + c8*8)
            = *(const uint4*)&sstage[row][c8*8];
    }
    if (tid < 128) {
        float s4 = spsum[0][tid] + spsum[1][tid] + spsum[2][tid] + spsum[3][tid];
        g_psum[((size_t)b*NMB + (m0>>7))*Nn + n0 + tid] = s4;
    }
}

// ---------------------------------------------------------------------------
// Kernel 3: AV + fused rowsum + fused BN partial stats. 3-stage, K-step 64.
// ---------------------------------------------------------------------------
#define AV_VOFF  16384
#define AV_STAGE (16384 + 18432)   // 34816
#define AV_SMEM  (3*AV_STAGE)      // 104448

__global__ void __launch_bounds__(256) k_av(
    const float* __restrict__ xr, const float* __restrict__ xi,
    const float* __restrict__ gamma)
{
    extern __shared__ __align__(16) unsigned char dyn[];
    const uint32_t base = s2u(dyn);

    const int tid = threadIdx.x;
    const int w = tid >> 5, lane = tid & 31;
    const int gr = lane >> 2, tg = lane & 3;
    const int wm = w & 3, wn = w >> 2;
    const int n0 = blockIdx.x * 128;
    const int d0 = blockIdx.y * 64;
    const int b  = blockIdx.z;

    const __nv_bfloat16* Ab  = g_attnb + (size_t)b*Nn*Nn;
    const __nv_bfloat16* vp[2] = { g_v[0] + (size_t)b*Nn*Cc, g_v[1] + (size_t)b*Nn*Cc };

    float accr[2][4][4], acci[2][4][4];
    #pragma unroll
    for (int mf=0; mf<2; ++mf)
        #pragma unroll
        for (int nf=0; nf<4; ++nf)
            #pragma unroll
            for (int e=0; e<4; ++e){ accr[mf][nf][e]=0.f; acci[mf][nf][e]=0.f; }

    auto load_stage = [&](int s, int mk){
        const uint32_t st = base + s*AV_STAGE;
        #pragma unroll
        for (int it=0; it<4; ++it){
            int idx = tid + 256*it;
            int r = idx>>3, c = idx&7;
            cpa16(sw128(st, r, c), Ab + (size_t)(n0+r)*Nn + mk + c*8);
        }
        #pragma unroll
        for (int it=0; it<4; ++it){
            int idx = tid + 256*it;
            int p = idx>>9, r = (idx>>3)&63, c = idx&7;
            cpa16(st + AV_VOFF + p*9216 + r*144 + c*16,
                  vp[p] + (size_t)(mk+r)*Cc + d0 + c*8);
        }
        CP_COMMIT();
    };

    load_stage(0, 0);
    load_stage(1, 64);

    const int NKT = Nn/64;   // 36
    for (int kt = 0; kt < NKT; ++kt) {
        const int s = kt % 3;
        if (kt < NKT-1) { CP_WAIT(1); } else { CP_WAIT(0); }
        __syncthreads();
        if (kt + 2 < NKT) load_stage((kt+2)%3, (kt+2)*64);

        const uint32_t st = base + s*AV_STAGE;
        #pragma unroll
        for (int ks=0; ks<64; ks+=16) {
            uint32_t a[2][4];
            #pragma unroll
            for (int mf=0; mf<2; ++mf) {
                int r = wm*32 + mf*16 + (lane&15);
                int c16 = (ks>>3) + (lane>>4);
                ldsm4(a[mf], sw128(st, r, c16));
            }
            #pragma unroll
            for (int nf2=0; nf2<2; ++nf2) {
                int cb = wn*32 + nf2*16;
                uint32_t bvr[4], bvi[4];
                uint32_t vaddr = st + AV_VOFF + (uint32_t)(ks + (lane&15))*144 + (uint32_t)(cb + (lane>>4)*8)*2;
                ldsm4t(bvr, vaddr);
                ldsm4t(bvi, vaddr + 9216);
                #pragma unroll
                for (int h=0; h<2; ++h) {
                    int nfr = nf2*2 + h;
                    #pragma unroll
                    for (int mf=0; mf<2; ++mf) {
                        mma16(accr[mf][nfr], a[mf], bvr + 2*h);
                        mma16(acci[mf][nfr], a[mf], bvi + 2*h);
                    }
                }
            }
        }
        __syncthreads();
    }

    // fused rowsum: 1/sum for this block's 128 rows (coalesced psum loads)
    float* srinv = (float*)(dyn + 20480);
    if (tid < 128) {
        float s = 0.f;
        #pragma unroll
        for (int mb=0; mb<NMB; ++mb)
            s += g_psum[((size_t)b*NMB + mb)*Nn + n0 + tid];
        srinv[tid] = 1.f / s;
    }
    __syncthreads();

    float rin[2][2];
    #pragma unroll
    for (int mf=0; mf<2; ++mf) {
        rin[mf][0] = srinv[wm*32 + mf*16 + gr];
        rin[mf][1] = srinv[wm*32 + mf*16 + gr + 8];
    }
    const float gma = gamma[0];

    // transpose epilogue -> g_outT [d][n] bf16 + coalesced fused BN stats
    __nv_bfloat16 (*stage)[144] = (__nv_bfloat16(*)[144])dyn;   // 18432 B (below srinv)
    const size_t basep = (size_t)b*Cc*Nn + (size_t)d0*Nn + n0;
    const int wi = b*NMB + blockIdx.x;
    #pragma unroll
    for (int p=0; p<2; ++p) {
        __syncthreads();
        #pragma unroll
        for (int mf=0; mf<2; ++mf) {
            int rl = wm*32 + mf*16 + gr;
            #pragma unroll
            for (int nfr=0; nfr<4; ++nfr) {
                int cl = wn*32 + nfr*8 + 2*tg;
                float* acc = p ? acci[mf][nfr] : accr[mf][nfr];
                stage[cl  ][rl  ] = __float2bfloat16(acc[0]*rin[mf][0]);
                stage[cl+1][rl  ] = __float2bfloat16(acc[1]*rin[mf][0]);
                stage[cl  ][rl+8] = __float2bfloat16(acc[2]*rin[mf][1]);
                stage[cl+1][rl+8] = __float2bfloat16(acc[3]*rin[mf][1]);
            }
        }
        __syncthreads();
        #pragma unroll
        for (int it=0; it<4; ++it) {
            int idx = tid + 256*it;
            int dl = idx >> 4, c8 = idx & 15;
            *(uint4*)(g_outT[p] + basep + (size_t)dl*Nn + c8*8) = *(const uint4*)&stage[dl][c8*8];
        }
        // coalesced fused BN partial stats: z = x + gamma*out(bf16)
        {
            const float* x = p ? xi : xr;
            #pragma unroll
            for (int it=0; it<4; ++it) {
                const int dl = (tid >> 4) + it*16;
                const int c8 = tid & 15;
                const float* xp = x + (size_t)b*Cc*Nn + (size_t)(d0+dl)*Nn + n0 + c8*8;
                float4 xv0 = *(const float4*)xp;
                float4 xv1 = *(const float4*)(xp + 4);
                const __nv_bfloat16* sp = &stage[dl][c8*8];
                float xs[8] = {xv0.x,xv0.y,xv0.z,xv0.w,xv1.x,xv1.y,xv1.z,xv1.w};
                float s = 0.f, ss = 0.f;
                #pragma unroll
                for (int j=0;j<8;++j){
                    float z = xs[j] + gma*__bfloat162float(sp[j]);
                    s += z; ss += z*z;
                }
                #pragma unroll
                for (int off=1; off<16; off<<=1){
                    s  += __shfl_xor_sync(0xFFFFFFFFu, s,  off);
                    ss += __shfl_xor_sync(0xFFFFFFFFu, ss, off);
                }
                if ((tid & 15) == 0) {
                    g_bnps[p][d0+dl][wi][0] = s;
                    g_bnps[p][d0+dl][wi][1] = ss;
                }
            }
        }
    }
}

// ---------------------------------------------------------------------------
// Kernel 4: BN stats reduce (144 partials per channel) -> mean, rstd
// ---------------------------------------------------------------------------
__global__ void __launch_bounds__(256) k_bnred()
{
    const int c = blockIdx.x, p = blockIdx.y;
    const int tid = threadIdx.x;
    float s = 0.f, ss = 0.f;
    if (tid < Bb*NMB) {
        s  = g_bnps[p][c][tid][0];
        ss = g_bnps[p][c][tid][1];
    }
    __shared__ float rs[256], rss[256];
    rs[tid] = s; rss[tid] = ss; __syncthreads();
    #pragma unroll
    for (int st = 128; st > 0; st >>= 1) {
        if (tid < st) { rs[tid] += rs[tid+st]; rss[tid] += rss[tid+st]; }
        __syncthreads();
    }
    if (tid == 0) {
        const float inv_cnt = 1.f / (float)Mtot;
        float mean = rs[0] * inv_cnt;
        float var  = rss[0] * inv_cnt - mean*mean;
        g_mean[p][c] = mean;
        g_rstd[p][c] = rsqrtf(var + EPSf);
    }
}

// ---------------------------------------------------------------------------
// Kernel 5: BN apply
// ---------------------------------------------------------------------------
__global__ void __launch_bounds__(256) k_bnapply(
    const float* __restrict__ xr, const float* __restrict__ xi,
    const float* __restrict__ gamma,
    const float* __restrict__ bnwr, const float* __restrict__ bnbr,
    const float* __restrict__ bnwi, const float* __restrict__ bnbi,
    float* __restrict__ out)
{
    const int idx4 = blockIdx.x*256 + threadIdx.x;
    const size_t e = (size_t)idx4 * 4;
    const size_t half = (size_t)Bb*Cc*Nn;
    const int p = (e >= half) ? 1 : 0;
    const size_t rem = e - (size_t)p*half;
    const int c = (int)((rem / Nn) % Cc);

    const float* x = p ? xi : xr;
    const float g = gamma[0];
    const float wsc = (p ? bnwi[c] : bnwr[c]) * g_rstd[p][c];
    const float bia = (p ? bnbi[c] : bnbr[c]);
    const float mu = g_mean[p][c];

    float4 xv = *(const float4*)(x + rem);
    uint2 ou = *(const uint2*)(g_outT[p] + rem);
    float2 o01 = __bfloat1622float2(*reinterpret_cast<const __nv_bfloat162*>(&ou.x));
    float2 o23 = __bfloat1622float2(*reinterpret_cast<const __nv_bfloat162*>(&ou.y));

    float4 r;
    r.x = (xv.x + g*o01.x - mu) * wsc + bia;
    r.y = (xv.y + g*o01.y - mu) * wsc + bia;
    r.z = (xv.z + g*o23.x - mu) * wsc + bia;
    r.w = (xv.w + g*o23.y - mu) * wsc + bia;
    *(float4*)(out + e) = r;
}

// ---------------------------------------------------------------------------
// Launch
// ---------------------------------------------------------------------------
extern "C" void kernel_launch(void* const* d_in, const int* in_sizes, int n_in,
                              void* d_out, int out_size)
{
    const float* xr   = (const float*)d_in[0];
    const float* xi   = (const float*)d_in[1];
    const float* q_wr = (const float*)d_in[2];
    const float* q_wi = (const float*)d_in[3];
    const float* q_br = (const float*)d_in[4];
    const float* q_bi = (const float*)d_in[5];
    const float* k_wr = (const float*)d_in[6];
    const float* k_wi = (const float*)d_in[7];
    const float* k_br = (const float*)d_in[8];
    const float* k_bi = (const float*)d_in[9];
    const float* v_wr = (const float*)d_in[10];
    const float* v_wi = (const float*)d_in[11];
    const float* v_br = (const float*)d_in[12];
    const float* v_bi = (const float*)d_in[13];
    const float* gamma= (const float*)d_in[14];
    const float* bnwr = (const float*)d_in[15];
    const float* bnbr = (const float*)d_in[16];
    const float* bnwi = (const float*)d_in[17];
    const float* bnbi = (const float*)d_in[18];
    float* out = (float*)d_out;

    cudaFuncSetAttribute(k_proj,   cudaFuncAttributeMaxDynamicSharedMemorySize, PJ_SMEM);
    cudaFuncSetAttribute(k_scores, cudaFuncAttributeMaxDynamicSharedMemorySize, SC_SMEM);
    cudaFuncSetAttribute(k_av,     cudaFuncAttributeMaxDynamicSharedMemorySize, AV_SMEM);

    k_cvtall<<<(unsigned)(XBLKS + WBLKS), 256>>>(xr, xi, q_wr, q_wi, k_wr, k_wi, v_wr, v_wi);

    k_proj<<<dim3(Mtot/128, Cc/64, 3), 256, PJ_SMEM>>>(q_br, q_bi, k_br, k_bi, v_br, v_bi);

    k_scores<<<dim3(Nn/128, Nn/128, Bb), 256, SC_SMEM>>>();
    k_av<<<dim3(Nn/128, Cc/64, Bb), 256, AV_SMEM>>>(xr, xi, gamma);

    k_bnred<<<dim3(Cc, 2), 256>>>();
    k_bnapply<<<(2*(size_t)Bb*Cc*Nn/4)/256, 256>>>(xr, xi, gamma, bnwr, bnbr, bnwi, bnbi, out);
}

// round 15
// speedup vs baseline: 1.1697x; 1.0009x over previous
#include <cuda_runtime.h>
#include <cuda_bf16.h>
#include <math.h>
#include <stdint.h>

#define Bb   8
#define Cc   256
#define Nn   2304
#define Mtot (Bb*Nn)
#define NMB  (Nn/128)      // 18 n-blocks
#define EPSf 1e-5f

// ---------------------------------------------------------------------------
// Scratch
// ---------------------------------------------------------------------------
__device__ __align__(128) __nv_bfloat16 g_xb[2][(size_t)Bb*Cc*Nn];   // bf16 X [p][b][c][n]
__device__ __align__(128) __nv_bfloat16 g_wb[6][(size_t)Cc*Cc];      // bf16 W
__device__ __align__(128) __nv_bfloat16 g_q[2][(size_t)Mtot*Cc];
__device__ __align__(128) __nv_bfloat16 g_k[2][(size_t)Mtot*Cc];
__device__ __align__(128) __nv_bfloat16 g_v[2][(size_t)Mtot*Cc];
__device__ __align__(128) __nv_bfloat16 g_attnb[(size_t)Bb*Nn*Nn];   // bf16 exp(S)
__device__ __align__(128) float g_psum[(size_t)Bb*NMB*Nn];           // partial row sums
__device__ __align__(128) __nv_bfloat16 g_outT[2][(size_t)Bb*Cc*Nn]; // bf16 [p][b][c][n]
__device__ __align__(128) float g_bnps[2][Cc][Bb*NMB][2];            // per-(c, part) (sum, sumsq)
__device__ float g_mean[2][Cc];
__device__ float g_rstd[2][Cc];

// ---------------------------------------------------------------------------
// helpers
// ---------------------------------------------------------------------------
__device__ __forceinline__ uint32_t s2u(const void* p){
    return (uint32_t)__cvta_generic_to_shared(p);
}
__device__ __forceinline__ uint32_t packbf(float lo, float hi){
    uint32_t r;
    asm("cvt.rn.bf16x2.f32 %0, %1, %2;" : "=r"(r) : "f"(hi), "f"(lo));
    return r;
}
__device__ __forceinline__ void mma16(float* d, const uint32_t* a, const uint32_t* b){
    asm volatile("mma.sync.aligned.m16n8k16.row.col.f32.bf16.bf16.f32 "
        "{%0,%1,%2,%3}, {%4,%5,%6,%7}, {%8,%9}, {%0,%1,%2,%3};"
        : "+f"(d[0]),"+f"(d[1]),"+f"(d[2]),"+f"(d[3])
        : "r"(a[0]),"r"(a[1]),"r"(a[2]),"r"(a[3]),"r"(b[0]),"r"(b[1]));
}
__device__ __forceinline__ void ldsm4(uint32_t* r, uint32_t addr){
    asm volatile("ldmatrix.sync.aligned.m8n8.x4.shared.b16 {%0,%1,%2,%3}, [%4];"
        : "=r"(r[0]),"=r"(r[1]),"=r"(r[2]),"=r"(r[3]) : "r"(addr));
}
__device__ __forceinline__ void ldsm4t(uint32_t* r, uint32_t addr){
    asm volatile("ldmatrix.sync.aligned.m8n8.x4.trans.shared.b16 {%0,%1,%2,%3}, [%4];"
        : "=r"(r[0]),"=r"(r[1]),"=r"(r[2]),"=r"(r[3]) : "r"(addr));
}
__device__ __forceinline__ void cpa16(uint32_t dst, const void* src){
    asm volatile("cp.async.cg.shared.global [%0], [%1], 16;" :: "r"(dst), "l"(src));
}
#define CP_COMMIT() asm volatile("cp.async.commit_group;")
#define CP_WAIT(N)  asm volatile("cp.async.wait_group %0;" :: "n"(N))

__device__ __forceinline__ uint32_t sw64(uint32_t tile, int r, int c16){
    return tile + (uint32_t)r*64u + (uint32_t)((c16 ^ ((r>>1)&3))<<4);
}
__device__ __forceinline__ uint32_t sw128(uint32_t tile, int r, int c16){
    return tile + (uint32_t)r*128u + (uint32_t)((c16 ^ (r&7))<<4);
}

// ---------------------------------------------------------------------------
// Kernel 0: convert X + 6 weight matrices fp32 -> bf16 (grid-split, 16/thread)
// ---------------------------------------------------------------------------
#define XBLKS ((2*(size_t)Bb*Cc*Nn/16)/256)   // 2304
#define WBLKS ((6*Cc*Cc/16)/256)              // 96

__global__ void __launch_bounds__(256) k_cvtall(
    const float* __restrict__ xr, const float* __restrict__ xi,
    const float* __restrict__ qwr, const float* __restrict__ qwi,
    const float* __restrict__ kwr, const float* __restrict__ kwi,
    const float* __restrict__ vwr, const float* __restrict__ vwi)
{
    const float* src;
    __nv_bfloat16* dst;
    size_t rem;
    if (blockIdx.x < XBLKS) {
        const size_t i16 = ((size_t)blockIdx.x*256 + threadIdx.x) * 16;
        const size_t half = (size_t)Bb*Cc*Nn;
        const int p = (i16 >= half) ? 1 : 0;
        rem = i16 - (size_t)p*half;
        src = p ? xi : xr;
        dst = g_xb[p];
    } else {
        const float* mats[6] = { qwr, qwi, kwr, kwi, vwr, vwi };
        __nv_bfloat16* dsts[6] = { g_wb[0], g_wb[1], g_wb[2], g_wb[3], g_wb[4], g_wb[5] };
        const int i16 = ((blockIdx.x - (int)XBLKS)*256 + threadIdx.x) * 16;
        const int mat = i16 >> 16;
        rem = (size_t)(i16 & 65535);
        src = mats[mat];
        dst = dsts[mat];
    }
    float4 a = *(const float4*)(src + rem);
    float4 b = *(const float4*)(src + rem + 4);
    float4 c = *(const float4*)(src + rem + 8);
    float4 d = *(const float4*)(src + rem + 12);
    uint4 o0, o1;
    o0.x = packbf(a.x,a.y); o0.y = packbf(a.z,a.w);
    o0.z = packbf(b.x,b.y); o0.w = packbf(b.z,b.w);
    o1.x = packbf(c.x,c.y); o1.y = packbf(c.z,c.w);
    o1.z = packbf(d.x,d.y); o1.w = packbf(d.z,d.w);
    *(uint4*)(dst + rem)     = o0;
    *(uint4*)(dst + rem + 8) = o1;
}

// ---------------------------------------------------------------------------
// Kernel 1: complex projection, cp.async 3-stage ring, K-step 32.
// ---------------------------------------------------------------------------
#define PJ_XPART 8704
#define PJ_WOFF  17408
#define PJ_WPART 4096
#define PJ_STAGE 25600
#define PJ_SMEM  (3*PJ_STAGE)

__global__ void __launch_bounds__(256) k_proj(
    const float* __restrict__ qbr, const float* __restrict__ qbi,
    const float* __restrict__ kbr, const float* __restrict__ kbi,
    const float* __restrict__ vbr, const float* __restrict__ vbi)
{
    extern __shared__ __align__(16) unsigned char dyn[];
    const uint32_t base = s2u(dyn);

    const int wsel = blockIdx.z;
    const float* brv = (wsel==0)?qbr:(wsel==1)?kbr:vbr;
    const float* biv = (wsel==0)?qbi:(wsel==1)?kbi:vbi;
    __nv_bfloat16* yr = (wsel==0)?g_q[0]:(wsel==1)?g_k[0]:g_v[0];
    __nv_bfloat16* yi = (wsel==0)?g_q[1]:(wsel==1)?g_k[1]:g_v[1];

    const int tid = threadIdx.x;
    const int w = tid >> 5, lane = tid & 31;
    const int gr = lane >> 2, tg = lane & 3;
    const int wm = w & 3, wn = w >> 2;
    const int m0 = blockIdx.x * 128;
    const int d0 = blockIdx.y * 64;
    const int b  = m0 / Nn;
    const int n0 = m0 - b*Nn;

    const __nv_bfloat16* xbp[2] = { g_xb[0] + (size_t)b*Cc*Nn, g_xb[1] + (size_t)b*Cc*Nn };
    const __nv_bfloat16* wbp[2] = { g_wb[wsel*2], g_wb[wsel*2+1] };

    float accr[2][4][4], acci[2][4][4];
    #pragma unroll
    for (int mf=0; mf<2; ++mf)
        #pragma unroll
        for (int nf=0; nf<4; ++nf)
            #pragma unroll
            for (int e=0; e<4; ++e){ accr[mf][nf][e]=0.f; acci[mf][nf][e]=0.f; }

    auto load_stage = [&](int s, int ck){
        const uint32_t st = base + s*PJ_STAGE;
        #pragma unroll
        for (int it=0; it<4; ++it){
            int idx = tid + 256*it;
            int p = idx>>9, r = (idx>>4)&31, c = idx&15;
            cpa16(st + p*PJ_XPART + r*272 + c*16,
                  xbp[p] + (size_t)(ck+r)*Nn + n0 + c*8);
        }
        #pragma unroll
        for (int it=0; it<2; ++it){
            int idx = tid + 256*it;
            int p = idx>>8, r = (idx>>2)&63, c = idx&3;
            cpa16(sw64(st + PJ_WOFF + p*PJ_WPART, r, c),
                  wbp[p] + (size_t)(d0+r)*Cc + ck + c*8);
        }
        CP_COMMIT();
    };

    load_stage(0, 0);
    load_stage(1, 32);

    for (int kt = 0; kt < 8; ++kt) {
        const int s = kt % 3;
        if (kt < 7) { CP_WAIT(1); } else { CP_WAIT(0); }
        __syncthreads();
        if (kt + 2 < 8) load_stage((kt+2)%3, (kt+2)*32);

        const uint32_t st = base + s*PJ_STAGE;
        #pragma unroll
        for (int ks=0; ks<32; ks+=16) {
            uint32_t axr[2][4], axi[2][4], ain[2][4];
            #pragma unroll
            for (int mf=0; mf<2; ++mf) {
                int crow = ks + (lane&7) + (lane>>4)*8;
                int mcol = wm*32 + mf*16 + ((lane>>3)&1)*8;
                ldsm4t(axr[mf], st + 0*PJ_XPART + (uint32_t)crow*272 + (uint32_t)mcol*2);
                ldsm4t(axi[mf], st + 1*PJ_XPART + (uint32_t)crow*272 + (uint32_t)mcol*2);
                #pragma unroll
                for (int e=0;e<4;++e) ain[mf][e] = axi[mf][e] ^ 0x80008000u;
            }
            #pragma unroll
            for (int nf2=0; nf2<2; ++nf2) {
                int rr = wn*32 + nf2*16 + (lane>>4)*8 + (lane&7);
                int c16 = (ks>>3) + ((lane>>3)&1);
                uint32_t bwr[4], bwi[4];
                ldsm4(bwr, sw64(st + PJ_WOFF,            rr, c16));
                ldsm4(bwi, sw64(st + PJ_WOFF + PJ_WPART, rr, c16));
                #pragma unroll
                for (int h=0; h<2; ++h) {
                    int nfr = nf2*2 + h;
                    #pragma unroll
                    for (int mf=0; mf<2; ++mf) {
                        mma16(accr[mf][nfr], axr[mf], bwr + 2*h);
                        mma16(accr[mf][nfr], ain[mf], bwi + 2*h);
                        mma16(acci[mf][nfr], axr[mf], bwi + 2*h);
                        mma16(acci[mf][nfr], axi[mf], bwr + 2*h);
                    }
                }
            }
        }
        __syncthreads();
    }

    // epilogue: stage bf16 [m 128][d 72-pitch], coalesced 16B writes
    __nv_bfloat16 (*pst)[72] = (__nv_bfloat16(*)[72])dyn;
    #pragma unroll
    for (int p=0; p<2; ++p) {
        __syncthreads();
        __nv_bfloat16* dst = p ? yi : yr;
        #pragma unroll
        for (int mf=0; mf<2; ++mf) {
            const int rl = wm*32 + mf*16 + gr;
            #pragma unroll
            for (int nfr=0; nfr<4; ++nfr) {
                const int cl = wn*32 + nfr*8 + 2*tg;
                const float b0 = p ? biv[d0+cl]   : brv[d0+cl];
                const float b1 = p ? biv[d0+cl+1] : brv[d0+cl+1];
                const float* acc = p ? acci[mf][nfr] : accr[mf][nfr];
                *(uint32_t*)&pst[rl  ][cl] = packbf(acc[0]+b0, acc[1]+b1);
                *(uint32_t*)&pst[rl+8][cl] = packbf(acc[2]+b0, acc[3]+b1);
            }
        }
        __syncthreads();
        #pragma unroll
        for (int it=0; it<4; ++it) {
            int idx = tid + 256*it;
            int row = idx >> 3, c8 = idx & 7;
            *(uint4*)(dst + (size_t)(m0+row)*Cc + d0 + c8*8) = *(const uint4*)&pst[row][c8*8];
        }
    }
}

// ---------------------------------------------------------------------------
// Kernel 2: scores + exp. Epilogue staged through smem, coalesced stores.
// ---------------------------------------------------------------------------
#define SC_STAGE 32768
#define SC_SMEM  (3*SC_STAGE)

__global__ void __launch_bounds__(256) k_scores()
{
    extern __shared__ __align__(16) unsigned char dyn[];
    const uint32_t base = s2u(dyn);

    const int tid = threadIdx.x;
    const int w = tid >> 5, lane = tid & 31;
    const int gr = lane >> 2, tg = lane & 3;
    const int wrow = w & 1, wcol = w >> 1;
    const int m0 = blockIdx.x * 128;
    const int n0 = blockIdx.y * 128;
    const int b  = blockIdx.z;

    const __nv_bfloat16* srcs[4] = {
        g_q[0] + (size_t)b*Nn*Cc, g_q[1] + (size_t)b*Nn*Cc,
        g_k[0] + (size_t)b*Nn*Cc, g_k[1] + (size_t)b*Nn*Cc };
    const int rbase[4] = { n0, n0, m0, m0 };

    float acc[4][4][4];
    #pragma unroll
    for (int mf=0; mf<4; ++mf)
        #pragma unroll
        for (int nf=0; nf<4; ++nf)
            #pragma unroll
            for (int e=0; e<4; ++e) acc[mf][nf][e]=0.f;

    auto load_stage = [&](int s, int ck){
        const uint32_t st = base + s*SC_STAGE;
        #pragma unroll
        for (int t=0;t<4;++t){
            const uint32_t tb = st + t*8192;
            #pragma unroll
            for (int it=0; it<2; ++it){
                int idx = tid + 256*it;
                int r = idx>>2, c = idx&3;
                cpa16(sw64(tb, r, c), srcs[t] + (size_t)(rbase[t]+r)*Cc + ck + c*8);
            }
        }
        CP_COMMIT();
    };

    load_stage(0, 0);
    load_stage(1, 32);

    for (int kt = 0; kt < 8; ++kt) {
        const int s = kt % 3;
        if (kt < 7) { CP_WAIT(1); } else { CP_WAIT(0); }
        __syncthreads();
        if (kt + 2 < 8) load_stage((kt+2)%3, (kt+2)*32);

        const uint32_t st = base + s*SC_STAGE;
        #pragma unroll
        for (int p=0; p<2; ++p) {
            const uint32_t qt = st + p*8192;
            const uint32_t ktile = st + 16384 + p*8192;
            #pragma unroll
            for (int ks=0; ks<32; ks+=16) {
                uint32_t a[4][4];
                #pragma unroll
                for (int mf=0; mf<4; ++mf) {
                    int r = wrow*64 + mf*16 + (lane&15);
                    int c16 = (ks>>3) + (lane>>4);
                    ldsm4(a[mf], sw64(qt, r, c16));
                }
                #pragma unroll
                for (int nf2=0; nf2<2; ++nf2) {
                    int rr = wcol*32 + nf2*16 + (lane>>4)*8 + (lane&7);
                    int c16 = (ks>>3) + ((lane>>3)&1);
                    uint32_t bb[4];
                    ldsm4(bb, sw64(ktile, rr, c16));
                    #pragma unroll
                    for (int mf=0; mf<4; ++mf) {
                        mma16(acc[mf][nf2*2  ], a[mf], bb);
                        mma16(acc[mf][nf2*2+1], a[mf], bb+2);
                    }
                }
            }
        }
        __syncthreads();
    }

    // epilogue: exp -> smem stage; partial row sums; coalesced writes
    __nv_bfloat16 (*sstage)[136] = (__nv_bfloat16(*)[136])dyn;
    float (*spsum)[128] = (float(*)[128])(dyn + 36864);
    const float sc = 1.0f/16.0f;
    #pragma unroll
    for (int mf=0; mf<4; ++mf) {
        const int rl = wrow*64 + mf*16 + gr;
        float p0 = 0.f, p1 = 0.f;
        #pragma unroll
        for (int nfr=0; nfr<4; ++nfr) {
            const int cl = wcol*32 + nfr*8 + 2*tg;
            float e0 = __expf(acc[mf][nfr][0]*sc);
            float e1 = __expf(acc[mf][nfr][1]*sc);
            float e2 = __expf(acc[mf][nfr][2]*sc);
            float e3 = __expf(acc[mf][nfr][3]*sc);
            *(uint32_t*)&sstage[rl  ][cl] = packbf(e0, e1);
            *(uint32_t*)&sstage[rl+8][cl] = packbf(e2, e3);
            p0 += e0 + e1;
            p1 += e2 + e3;
        }
        p0 += __shfl_xor_sync(0xFFFFFFFFu, p0, 1);
        p0 += __shfl_xor_sync(0xFFFFFFFFu, p0, 2);
        p1 += __shfl_xor_sync(0xFFFFFFFFu, p1, 1);
        p1 += __shfl_xor_sync(0xFFFFFFFFu, p1, 2);
        if (tg == 0) {
            spsum[wcol][rl    ] = p0;
            spsum[wcol][rl + 8] = p1;
        }
    }
    __syncthreads();
    #pragma unroll
    for (int it=0; it<8; ++it) {
        int idx = tid + 256*it;
        int row = idx >> 4, c8 = idx & 15;
        *(uint4*)(g_attnb + (size_t)b*Nn*Nn + (size_t)(n0+row)*Nn + m0 + c8*8)
            = *(const uint4*)&sstage[row][c8*8];
    }
    if (tid < 128) {
        float s4 = spsum[0][tid] + spsum[1][tid] + spsum[2][tid] + spsum[3][tid];
        g_psum[((size_t)b*NMB + (m0>>7))*Nn + n0 + tid] = s4;
    }
}

// ---------------------------------------------------------------------------
// Kernel 3: AV + fused rowsum (hoisted to prologue) + fused BN stats.
// ---------------------------------------------------------------------------
#define AV_VOFF  16384
#define AV_STAGE (16384 + 18432)       // 34816
#define AV_RINV  (3*AV_STAGE)          // 104448 (dedicated, no aliasing)
#define AV_SMEM  (3*AV_STAGE + 512)    // 104960

__global__ void __launch_bounds__(256) k_av(
    const float* __restrict__ xr, const float* __restrict__ xi,
    const float* __restrict__ gamma)
{
    extern __shared__ __align__(16) unsigned char dyn[];
    const uint32_t base = s2u(dyn);

    const int tid = threadIdx.x;
    const int w = tid >> 5, lane = tid & 31;
    const int gr = lane >> 2, tg = lane & 3;
    const int wm = w & 3, wn = w >> 2;
    const int n0 = blockIdx.x * 128;
    const int d0 = blockIdx.y * 64;
    const int b  = blockIdx.z;

    const __nv_bfloat16* Ab  = g_attnb + (size_t)b*Nn*Nn;
    const __nv_bfloat16* vp[2] = { g_v[0] + (size_t)b*Nn*Cc, g_v[1] + (size_t)b*Nn*Cc };

    float accr[2][4][4], acci[2][4][4];
    #pragma unroll
    for (int mf=0; mf<2; ++mf)
        #pragma unroll
        for (int nf=0; nf<4; ++nf)
            #pragma unroll
            for (int e=0; e<4; ++e){ accr[mf][nf][e]=0.f; acci[mf][nf][e]=0.f; }

    auto load_stage = [&](int s, int mk){
        const uint32_t st = base + s*AV_STAGE;
        #pragma unroll
        for (int it=0; it<4; ++it){
            int idx = tid + 256*it;
            int r = idx>>3, c = idx&7;
            cpa16(sw128(st, r, c), Ab + (size_t)(n0+r)*Nn + mk + c*8);
        }
        #pragma unroll
        for (int it=0; it<4; ++it){
            int idx = tid + 256*it;
            int p = idx>>9, r = (idx>>3)&63, c = idx&7;
            cpa16(st + AV_VOFF + p*9216 + r*144 + c*16,
                  vp[p] + (size_t)(mk+r)*Cc + d0 + c*8);
        }
        CP_COMMIT();
    };

    load_stage(0, 0);
    load_stage(1, 64);

    // hoisted rowsum: overlaps with prologue TMA-less cp.async loads
    float* srinv = (float*)(dyn + AV_RINV);
    if (tid < 128) {
        float s = 0.f;
        #pragma unroll
        for (int mb=0; mb<NMB; ++mb)
            s += g_psum[((size_t)b*NMB + mb)*Nn + n0 + tid];
        srinv[tid] = 1.f / s;
    }

    const int NKT = Nn/64;   // 36
    for (int kt = 0; kt < NKT; ++kt) {
        const int s = kt % 3;
        if (kt < NKT-1) { CP_WAIT(1); } else { CP_WAIT(0); }
        __syncthreads();
        if (kt + 2 < NKT) load_stage((kt+2)%3, (kt+2)*64);

        const uint32_t st = base + s*AV_STAGE;
        #pragma unroll
        for (int ks=0; ks<64; ks+=16) {
            uint32_t a[2][4];
            #pragma unroll
            for (int mf=0; mf<2; ++mf) {
                int r = wm*32 + mf*16 + (lane&15);
                int c16 = (ks>>3) + (lane>>4);
                ldsm4(a[mf], sw128(st, r, c16));
            }
            #pragma unroll
            for (int nf2=0; nf2<2; ++nf2) {
                int cb = wn*32 + nf2*16;
                uint32_t bvr[4], bvi[4];
                uint32_t vaddr = st + AV_VOFF + (uint32_t)(ks + (lane&15))*144 + (uint32_t)(cb + (lane>>4)*8)*2;
                ldsm4t(bvr, vaddr);
                ldsm4t(bvi, vaddr + 9216);
                #pragma unroll
                for (int h=0; h<2; ++h) {
                    int nfr = nf2*2 + h;
                    #pragma unroll
                    for (int mf=0; mf<2; ++mf) {
                        mma16(accr[mf][nfr], a[mf], bvr + 2*h);
                        mma16(acci[mf][nfr], a[mf], bvi + 2*h);
                    }
                }
            }
        }
        __syncthreads();
    }

    float rin[2][2];
    #pragma unroll
    for (int mf=0; mf<2; ++mf) {
        rin[mf][0] = srinv[wm*32 + mf*16 + gr];
        rin[mf][1] = srinv[wm*32 + mf*16 + gr + 8];
    }
    const float gma = gamma[0];

    // transpose epilogue -> g_outT [d][n] bf16 + coalesced fused BN stats
    __nv_bfloat16 (*stage)[144] = (__nv_bfloat16(*)[144])dyn;
    const size_t basep = (size_t)b*Cc*Nn + (size_t)d0*Nn + n0;
    const int wi = b*NMB + blockIdx.x;
    #pragma unroll
    for (int p=0; p<2; ++p) {
        __syncthreads();
        #pragma unroll
        for (int mf=0; mf<2; ++mf) {
            int rl = wm*32 + mf*16 + gr;
            #pragma unroll
            for (int nfr=0; nfr<4; ++nfr) {
                int cl = wn*32 + nfr*8 + 2*tg;
                float* acc = p ? acci[mf][nfr] : accr[mf][nfr];
                stage[cl  ][rl  ] = __float2bfloat16(acc[0]*rin[mf][0]);
                stage[cl+1][rl  ] = __float2bfloat16(acc[1]*rin[mf][0]);
                stage[cl  ][rl+8] = __float2bfloat16(acc[2]*rin[mf][1]);
                stage[cl+1][rl+8] = __float2bfloat16(acc[3]*rin[mf][1]);
            }
        }
        __syncthreads();
        #pragma unroll
        for (int it=0; it<4; ++it) {
            int idx = tid + 256*it;
            int dl = idx >> 4, c8 = idx & 15;
            *(uint4*)(g_outT[p] + basep + (size_t)dl*Nn + c8*8) = *(const uint4*)&stage[dl][c8*8];
        }
        {
            const float* x = p ? xi : xr;
            #pragma unroll
            for (int it=0; it<4; ++it) {
                const int dl = (tid >> 4) + it*16;
                const int c8 = tid & 15;
                const float* xp = x + (size_t)b*Cc*Nn + (size_t)(d0+dl)*Nn + n0 + c8*8;
                float4 xv0 = *(const float4*)xp;
                float4 xv1 = *(const float4*)(xp + 4);
                const __nv_bfloat16* sp = &stage[dl][c8*8];
                float xs[8] = {xv0.x,xv0.y,xv0.z,xv0.w,xv1.x,xv1.y,xv1.z,xv1.w};
                float s = 0.f, ss = 0.f;
                #pragma unroll
                for (int j=0;j<8;++j){
                    float z = xs[j] + gma*__bfloat162float(sp[j]);
                    s += z; ss += z*z;
                }
                #pragma unroll
                for (int off=1; off<16; off<<=1){
                    s  += __shfl_xor_sync(0xFFFFFFFFu, s,  off);
                    ss += __shfl_xor_sync(0xFFFFFFFFu, ss, off);
                }
                if ((tid & 15) == 0) {
                    g_bnps[p][d0+dl][wi][0] = s;
                    g_bnps[p][d0+dl][wi][1] = ss;
                }
            }
        }
    }
}

// ---------------------------------------------------------------------------
// Kernel 4: BN stats reduce -> mean, rstd
// ---------------------------------------------------------------------------
__global__ void __launch_bounds__(256) k_bnred()
{
    const int c = blockIdx.x, p = blockIdx.y;
    const int tid = threadIdx.x;
    float s = 0.f, ss = 0.f;
    if (tid < Bb*NMB) {
        s  = g_bnps[p][c][tid][0];
        ss = g_bnps[p][c][tid][1];
    }
    __shared__ float rs[256], rss[256];
    rs[tid] = s; rss[tid] = ss; __syncthreads();
    #pragma unroll
    for (int st = 128; st > 0; st >>= 1) {
        if (tid < st) { rs[tid] += rs[tid+st]; rss[tid] += rss[tid+st]; }
        __syncthreads();
    }
    if (tid == 0) {
        const float inv_cnt = 1.f / (float)Mtot;
        float mean = rs[0] * inv_cnt;
        float var  = rss[0] * inv_cnt - mean*mean;
        g_mean[p][c] = mean;
        g_rstd[p][c] = rsqrtf(var + EPSf);
    }
}

// ---------------------------------------------------------------------------
// Kernel 5: BN apply (8 elems/thread)
// ---------------------------------------------------------------------------
__global__ void __launch_bounds__(256) k_bnapply(
    const float* __restrict__ xr, const float* __restrict__ xi,
    const float* __restrict__ gamma,
    const float* __restrict__ bnwr, const float* __restrict__ bnbr,
    const float* __restrict__ bnwi, const float* __restrict__ bnbi,
    float* __restrict__ out)
{
    const size_t e = ((size_t)blockIdx.x*256 + threadIdx.x) * 8;
    const size_t half = (size_t)Bb*Cc*Nn;
    const int p = (e >= half) ? 1 : 0;
    const size_t rem = e - (size_t)p*half;
    const int c = (int)((rem / Nn) % Cc);

    const float* x = p ? xi : xr;
    const float g = gamma[0];
    const float wsc = (p ? bnwi[c] : bnwr[c]) * g_rstd[p][c];
    const float bia = (p ? bnbi[c] : bnbr[c]);
    const float mu = g_mean[p][c];

    float4 xv0 = *(const float4*)(x + rem);
    float4 xv1 = *(const float4*)(x + rem + 4);
    uint4 ou = *(const uint4*)(g_outT[p] + rem);
    float2 o01 = __bfloat1622float2(*reinterpret_cast<const __nv_bfloat162*>(&ou.x));
    float2 o23 = __bfloat1622float2(*reinterpret_cast<const __nv_bfloat162*>(&ou.y));
    float2 o45 = __bfloat1622float2(*reinterpret_cast<const __nv_bfloat162*>(&ou.z));
    float2 o67 = __bfloat1622float2(*reinterpret_cast<const __nv_bfloat162*>(&ou.w));

    float4 r0, r1;
    r0.x = (xv0.x + g*o01.x - mu) * wsc + bia;
    r0.y = (xv0.y + g*o01.y - mu) * wsc + bia;
    r0.z = (xv0.z + g*o23.x - mu) * wsc + bia;
    r0.w = (xv0.w + g*o23.y - mu) * wsc + bia;
    r1.x = (xv1.x + g*o45.x - mu) * wsc + bia;
    r1.y = (xv1.y + g*o45.y - mu) * wsc + bia;
    r1.z = (xv1.z + g*o67.x - mu) * wsc + bia;
    r1.w = (xv1.w + g*o67.y - mu) * wsc + bia;
    *(float4*)(out + e)     = r0;
    *(float4*)(out + e + 4) = r1;
}

// ---------------------------------------------------------------------------
// Launch
// ---------------------------------------------------------------------------
extern "C" void kernel_launch(void* const* d_in, const int* in_sizes, int n_in,
                              void* d_out, int out_size)
{
    const float* xr   = (const float*)d_in[0];
    const float* xi   = (const float*)d_in[1];
    const float* q_wr = (const float*)d_in[2];
    const float* q_wi = (const float*)d_in[3];
    const float* q_br = (const float*)d_in[4];
    const float* q_bi = (const float*)d_in[5];
    const float* k_wr = (const float*)d_in[6];
    const float* k_wi = (const float*)d_in[7];
    const float* k_br = (const float*)d_in[8];
    const float* k_bi = (const float*)d_in[9];
    const float* v_wr = (const float*)d_in[10];
    const float* v_wi = (const float*)d_in[11];
    const float* v_br = (const float*)d_in[12];
    const float* v_bi = (const float*)d_in[13];
    const float* gamma= (const float*)d_in[14];
    const float* bnwr = (const float*)d_in[15];
    const float* bnbr = (const float*)d_in[16];
    const float* bnwi = (const float*)d_in[17];
    const float* bnbi = (const float*)d_in[18];
    float* out = (float*)d_out;

    cudaFuncSetAttribute(k_proj,   cudaFuncAttributeMaxDynamicSharedMemorySize, PJ_SMEM);
    cudaFuncSetAttribute(k_scores, cudaFuncAttributeMaxDynamicSharedMemorySize, SC_SMEM);
    cudaFuncSetAttribute(k_av,     cudaFuncAttributeMaxDynamicSharedMemorySize, AV_SMEM);

    k_cvtall<<<(unsigned)(XBLKS + WBLKS), 256>>>(xr, xi, q_wr, q_wi, k_wr, k_wi, v_wr, v_wi);

    k_proj<<<dim3(Mtot/128, Cc/64, 3), 256, PJ_SMEM>>>(q_br, q_bi, k_br, k_bi, v_br, v_bi);

    k_scores<<<dim3(Nn/128, Nn/128, Bb), 256, SC_SMEM>>>();
    k_av<<<dim3(Nn/128, Cc/64, Bb), 256, AV_SMEM>>>(xr, xi, gamma);

    k_bnred<<<dim3(Cc, 2), 256>>>();
    k_bnapply<<<(2*(size_t)Bb*Cc*Nn/8)/256, 256>>>(xr, xi, gamma, bnwr, bnbr, bnwi, bnbi, out);
}

// round 16
// speedup vs baseline: 1.2033x; 1.0287x over previous
#include <cuda_runtime.h>
#include <cuda_bf16.h>
#include <math.h>
#include <stdint.h>

#define Bb   8
#define Cc   256
#define Nn   2304
#define Mtot (Bb*Nn)
#define NMB  (Nn/256)      // 9 m-blocks (scores block covers 256 m)
#define EPSf 1e-5f

// ---------------------------------------------------------------------------
// Scratch
// ---------------------------------------------------------------------------
__device__ __align__(128) __nv_bfloat16 g_xb[2][(size_t)Bb*Cc*Nn];
__device__ __align__(128) __nv_bfloat16 g_wb[6][(size_t)Cc*Cc];
__device__ __align__(128) __nv_bfloat16 g_q[2][(size_t)Mtot*Cc];
__device__ __align__(128) __nv_bfloat16 g_k[2][(size_t)Mtot*Cc];
__device__ __align__(128) __nv_bfloat16 g_v[2][(size_t)Mtot*Cc];
__device__ __align__(128) __nv_bfloat16 g_attnb[(size_t)Bb*Nn*Nn];
__device__ __align__(128) float g_psum[(size_t)Bb*NMB*Nn];
__device__ __align__(128) __nv_bfloat16 g_outT[2][(size_t)Bb*Cc*Nn];
__device__ __align__(128) float g_bnps[2][Cc][Bb*18][2];   // AV partials (18 n-blocks)
__device__ float g_mean[2][Cc];
__device__ float g_rstd[2][Cc];

// ---------------------------------------------------------------------------
// helpers
// ---------------------------------------------------------------------------
__device__ __forceinline__ uint32_t s2u(const void* p){
    return (uint32_t)__cvta_generic_to_shared(p);
}
__device__ __forceinline__ uint32_t packbf(float lo, float hi){
    uint32_t r;
    asm("cvt.rn.bf16x2.f32 %0, %1, %2;" : "=r"(r) : "f"(hi), "f"(lo));
    return r;
}
__device__ __forceinline__ void mma16(float* d, const uint32_t* a, const uint32_t* b){
    asm volatile("mma.sync.aligned.m16n8k16.row.col.f32.bf16.bf16.f32 "
        "{%0,%1,%2,%3}, {%4,%5,%6,%7}, {%8,%9}, {%0,%1,%2,%3};"
        : "+f"(d[0]),"+f"(d[1]),"+f"(d[2]),"+f"(d[3])
        : "r"(a[0]),"r"(a[1]),"r"(a[2]),"r"(a[3]),"r"(b[0]),"r"(b[1]));
}
__device__ __forceinline__ void ldsm4(uint32_t* r, uint32_t addr){
    asm volatile("ldmatrix.sync.aligned.m8n8.x4.shared.b16 {%0,%1,%2,%3}, [%4];"
        : "=r"(r[0]),"=r"(r[1]),"=r"(r[2]),"=r"(r[3]) : "r"(addr));
}
__device__ __forceinline__ void ldsm4t(uint32_t* r, uint32_t addr){
    asm volatile("ldmatrix.sync.aligned.m8n8.x4.trans.shared.b16 {%0,%1,%2,%3}, [%4];"
        : "=r"(r[0]),"=r"(r[1]),"=r"(r[2]),"=r"(r[3]) : "r"(addr));
}
__device__ __forceinline__ void cpa16(uint32_t dst, const void* src){
    asm volatile("cp.async.cg.shared.global [%0], [%1], 16;" :: "r"(dst), "l"(src));
}
#define CP_COMMIT() asm volatile("cp.async.commit_group;")
#define CP_WAIT(N)  asm volatile("cp.async.wait_group %0;" :: "n"(N))

__device__ __forceinline__ uint32_t sw64(uint32_t tile, int r, int c16){
    return tile + (uint32_t)r*64u + (uint32_t)((c16 ^ ((r>>1)&3))<<4);
}
__device__ __forceinline__ uint32_t sw128(uint32_t tile, int r, int c16){
    return tile + (uint32_t)r*128u + (uint32_t)((c16 ^ (r&7))<<4);
}

// ---------------------------------------------------------------------------
// Kernel 0: convert X + 6 weight matrices fp32 -> bf16 (grid-split, 16/thread)
// ---------------------------------------------------------------------------
#define XBLKS ((2*(size_t)Bb*Cc*Nn/16)/256)   // 2304
#define WBLKS ((6*Cc*Cc/16)/256)              // 96

__global__ void __launch_bounds__(256) k_cvtall(
    const float* __restrict__ xr, const float* __restrict__ xi,
    const float* __restrict__ qwr, const float* __restrict__ qwi,
    const float* __restrict__ kwr, const float* __restrict__ kwi,
    const float* __restrict__ vwr, const float* __restrict__ vwi)
{
    const float* src;
    __nv_bfloat16* dst;
    size_t rem;
    if (blockIdx.x < XBLKS) {
        const size_t i16 = ((size_t)blockIdx.x*256 + threadIdx.x) * 16;
        const size_t half = (size_t)Bb*Cc*Nn;
        const int p = (i16 >= half) ? 1 : 0;
        rem = i16 - (size_t)p*half;
        src = p ? xi : xr;
        dst = g_xb[p];
    } else {
        const float* mats[6] = { qwr, qwi, kwr, kwi, vwr, vwi };
        __nv_bfloat16* dsts[6] = { g_wb[0], g_wb[1], g_wb[2], g_wb[3], g_wb[4], g_wb[5] };
        const int i16 = ((blockIdx.x - (int)XBLKS)*256 + threadIdx.x) * 16;
        const int mat = i16 >> 16;
        rem = (size_t)(i16 & 65535);
        src = mats[mat];
        dst = dsts[mat];
    }
    float4 a = *(const float4*)(src + rem);
    float4 b = *(const float4*)(src + rem + 4);
    float4 c = *(const float4*)(src + rem + 8);
    float4 d = *(const float4*)(src + rem + 12);
    uint4 o0, o1;
    o0.x = packbf(a.x,a.y); o0.y = packbf(a.z,a.w);
    o0.z = packbf(b.x,b.y); o0.w = packbf(b.z,b.w);
    o1.x = packbf(c.x,c.y); o1.y = packbf(c.z,c.w);
    o1.z = packbf(d.x,d.y); o1.w = packbf(d.z,d.w);
    *(uint4*)(dst + rem)     = o0;
    *(uint4*)(dst + rem + 8) = o1;
}

// ---------------------------------------------------------------------------
// Kernel 1: complex projection, cp.async 3-stage ring, K-step 32.
// ---------------------------------------------------------------------------
#define PJ_XPART 8704
#define PJ_WOFF  17408
#define PJ_WPART 4096
#define PJ_STAGE 25600
#define PJ_SMEM  (3*PJ_STAGE)

__global__ void __launch_bounds__(256) k_proj(
    const float* __restrict__ qbr, const float* __restrict__ qbi,
    const float* __restrict__ kbr, const float* __restrict__ kbi,
    const float* __restrict__ vbr, const float* __restrict__ vbi)
{
    extern __shared__ __align__(16) unsigned char dyn[];
    const uint32_t base = s2u(dyn);

    const int wsel = blockIdx.z;
    const float* brv = (wsel==0)?qbr:(wsel==1)?kbr:vbr;
    const float* biv = (wsel==0)?qbi:(wsel==1)?kbi:vbi;
    __nv_bfloat16* yr = (wsel==0)?g_q[0]:(wsel==1)?g_k[0]:g_v[0];
    __nv_bfloat16* yi = (wsel==0)?g_q[1]:(wsel==1)?g_k[1]:g_v[1];

    const int tid = threadIdx.x;
    const int w = tid >> 5, lane = tid & 31;
    const int gr = lane >> 2, tg = lane & 3;
    const int wm = w & 3, wn = w >> 2;
    const int m0 = blockIdx.x * 128;
    const int d0 = blockIdx.y * 64;
    const int b  = m0 / Nn;
    const int n0 = m0 - b*Nn;

    const __nv_bfloat16* xbp[2] = { g_xb[0] + (size_t)b*Cc*Nn, g_xb[1] + (size_t)b*Cc*Nn };
    const __nv_bfloat16* wbp[2] = { g_wb[wsel*2], g_wb[wsel*2+1] };

    float accr[2][4][4], acci[2][4][4];
    #pragma unroll
    for (int mf=0; mf<2; ++mf)
        #pragma unroll
        for (int nf=0; nf<4; ++nf)
            #pragma unroll
            for (int e=0; e<4; ++e){ accr[mf][nf][e]=0.f; acci[mf][nf][e]=0.f; }

    auto load_stage = [&](int s, int ck){
        const uint32_t st = base + s*PJ_STAGE;
        #pragma unroll
        for (int it=0; it<4; ++it){
            int idx = tid + 256*it;
            int p = idx>>9, r = (idx>>4)&31, c = idx&15;
            cpa16(st + p*PJ_XPART + r*272 + c*16,
                  xbp[p] + (size_t)(ck+r)*Nn + n0 + c*8);
        }
        #pragma unroll
        for (int it=0; it<2; ++it){
            int idx = tid + 256*it;
            int p = idx>>8, r = (idx>>2)&63, c = idx&3;
            cpa16(sw64(st + PJ_WOFF + p*PJ_WPART, r, c),
                  wbp[p] + (size_t)(d0+r)*Cc + ck + c*8);
        }
        CP_COMMIT();
    };

    load_stage(0, 0);
    load_stage(1, 32);

    for (int kt = 0; kt < 8; ++kt) {
        const int s = kt % 3;
        if (kt < 7) { CP_WAIT(1); } else { CP_WAIT(0); }
        __syncthreads();
        if (kt + 2 < 8) load_stage((kt+2)%3, (kt+2)*32);

        const uint32_t st = base + s*PJ_STAGE;
        #pragma unroll
        for (int ks=0; ks<32; ks+=16) {
            uint32_t axr[2][4], axi[2][4], ain[2][4];
            #pragma unroll
            for (int mf=0; mf<2; ++mf) {
                int crow = ks + (lane&7) + (lane>>4)*8;
                int mcol = wm*32 + mf*16 + ((lane>>3)&1)*8;
                ldsm4t(axr[mf], st + 0*PJ_XPART + (uint32_t)crow*272 + (uint32_t)mcol*2);
                ldsm4t(axi[mf], st + 1*PJ_XPART + (uint32_t)crow*272 + (uint32_t)mcol*2);
                #pragma unroll
                for (int e=0;e<4;++e) ain[mf][e] = axi[mf][e] ^ 0x80008000u;
            }
            #pragma unroll
            for (int nf2=0; nf2<2; ++nf2) {
                int rr = wn*32 + nf2*16 + (lane>>4)*8 + (lane&7);
                int c16 = (ks>>3) + ((lane>>3)&1);
                uint32_t bwr[4], bwi[4];
                ldsm4(bwr, sw64(st + PJ_WOFF,            rr, c16));
                ldsm4(bwi, sw64(st + PJ_WOFF + PJ_WPART, rr, c16));
                #pragma unroll
                for (int h=0; h<2; ++h) {
                    int nfr = nf2*2 + h;
                    #pragma unroll
                    for (int mf=0; mf<2; ++mf) {
                        mma16(accr[mf][nfr], axr[mf], bwr + 2*h);
                        mma16(accr[mf][nfr], ain[mf], bwi + 2*h);
                        mma16(acci[mf][nfr], axr[mf], bwi + 2*h);
                        mma16(acci[mf][nfr], axi[mf], bwr + 2*h);
                    }
                }
            }
        }
        __syncthreads();
    }

    // epilogue: stage bf16 [m 128][d 72-pitch], coalesced 16B writes
    __nv_bfloat16 (*pst)[72] = (__nv_bfloat16(*)[72])dyn;
    #pragma unroll
    for (int p=0; p<2; ++p) {
        __syncthreads();
        __nv_bfloat16* dst = p ? yi : yr;
        #pragma unroll
        for (int mf=0; mf<2; ++mf) {
            const int rl = wm*32 + mf*16 + gr;
            #pragma unroll
            for (int nfr=0; nfr<4; ++nfr) {
                const int cl = wn*32 + nfr*8 + 2*tg;
                const float b0 = p ? biv[d0+cl]   : brv[d0+cl];
                const float b1 = p ? biv[d0+cl+1] : brv[d0+cl+1];
                const float* acc = p ? acci[mf][nfr] : accr[mf][nfr];
                *(uint32_t*)&pst[rl  ][cl] = packbf(acc[0]+b0, acc[1]+b1);
                *(uint32_t*)&pst[rl+8][cl] = packbf(acc[2]+b0, acc[3]+b1);
            }
        }
        __syncthreads();
        #pragma unroll
        for (int it=0; it<4; ++it) {
            int idx = tid + 256*it;
            int row = idx >> 3, c8 = idx & 7;
            *(uint4*)(dst + (size_t)(m0+row)*Cc + d0 + c8*8) = *(const uint4*)&pst[row][c8*8];
        }
    }
}

// ---------------------------------------------------------------------------
// Kernel 2: scores + exp. Block 128n x 256m, 16 warps (2 n x 8 m),
//   per-warp tile 64x32. 3-stage ring, K-step 32 per part.
//   Stage: [Q0 8K | Q1 8K | K0 16K | K1 16K] = 48K.
// ---------------------------------------------------------------------------
#define SC_STAGE 49152
#define SC_SMEM  (3*SC_STAGE)

__global__ void __launch_bounds__(512) k_scores()
{
    extern __shared__ __align__(16) unsigned char dyn[];
    const uint32_t base = s2u(dyn);

    const int tid = threadIdx.x;
    const int w = tid >> 5, lane = tid & 31;
    const int gr = lane >> 2, tg = lane & 3;
    const int wrow = w & 1, wcol = w >> 1;     // wcol 0..7
    const int m0 = blockIdx.x * 256;
    const int n0 = blockIdx.y * 128;
    const int b  = blockIdx.z;

    const __nv_bfloat16* qp[2] = { g_q[0] + (size_t)b*Nn*Cc, g_q[1] + (size_t)b*Nn*Cc };
    const __nv_bfloat16* kp[2] = { g_k[0] + (size_t)b*Nn*Cc, g_k[1] + (size_t)b*Nn*Cc };

    float acc[4][4][4];
    #pragma unroll
    for (int mf=0; mf<4; ++mf)
        #pragma unroll
        for (int nf=0; nf<4; ++nf)
            #pragma unroll
            for (int e=0; e<4; ++e) acc[mf][nf][e]=0.f;

    auto load_stage = [&](int s, int ck){
        const uint32_t st = base + s*SC_STAGE;
        #pragma unroll
        for (int it=0; it<2; ++it){            // Q: 2p x 128r x 4c = 1024
            int idx = tid + 512*it;
            int p = idx>>9, r = (idx>>2)&127, c = idx&3;
            cpa16(sw64(st + p*8192, r, c), qp[p] + (size_t)(n0+r)*Cc + ck + c*8);
        }
        #pragma unroll
        for (int it=0; it<4; ++it){            // K: 2p x 256r x 4c = 2048
            int idx = tid + 512*it;
            int p = idx>>10, r = (idx>>2)&255, c = idx&3;
            cpa16(sw64(st + 16384 + p*16384, r, c), kp[p] + (size_t)(m0+r)*Cc + ck + c*8);
        }
        CP_COMMIT();
    };

    load_stage(0, 0);
    load_stage(1, 32);

    for (int kt = 0; kt < 8; ++kt) {
        const int s = kt % 3;
        if (kt < 7) { CP_WAIT(1); } else { CP_WAIT(0); }
        __syncthreads();
        if (kt + 2 < 8) load_stage((kt+2)%3, (kt+2)*32);

        const uint32_t st = base + s*SC_STAGE;
        #pragma unroll
        for (int p=0; p<2; ++p) {
            const uint32_t qt = st + p*8192;
            const uint32_t ktile = st + 16384 + p*16384;
            #pragma unroll
            for (int ks=0; ks<32; ks+=16) {
                uint32_t a[4][4];
                #pragma unroll
                for (int mf=0; mf<4; ++mf) {
                    int r = wrow*64 + mf*16 + (lane&15);
                    int c16 = (ks>>3) + (lane>>4);
                    ldsm4(a[mf], sw64(qt, r, c16));
                }
                #pragma unroll
                for (int nf2=0; nf2<2; ++nf2) {
                    int rr = wcol*32 + nf2*16 + (lane>>4)*8 + (lane&7);
                    int c16 = (ks>>3) + ((lane>>3)&1);
                    uint32_t bb[4];
                    ldsm4(bb, sw64(ktile, rr, c16));
                    #pragma unroll
                    for (int mf=0; mf<4; ++mf) {
                        mma16(acc[mf][nf2*2  ], a[mf], bb);
                        mma16(acc[mf][nf2*2+1], a[mf], bb+2);
                    }
                }
            }
        }
        __syncthreads();
    }

    // epilogue: exp -> smem stage [128][280 pitch]; partial sums; coalesced out
    __nv_bfloat16 (*sstage)[280] = (__nv_bfloat16(*)[280])dyn;    // 71680 B
    float (*spsum)[128] = (float(*)[128])(dyn + 71680);           // [8][128]
    const float sc = 1.0f/16.0f;
    #pragma unroll
    for (int mf=0; mf<4; ++mf) {
        const int rl = wrow*64 + mf*16 + gr;
        float p0 = 0.f, p1 = 0.f;
        #pragma unroll
        for (int nfr=0; nfr<4; ++nfr) {
            const int cl = wcol*32 + nfr*8 + 2*tg;
            float e0 = __expf(acc[mf][nfr][0]*sc);
            float e1 = __expf(acc[mf][nfr][1]*sc);
            float e2 = __expf(acc[mf][nfr][2]*sc);
            float e3 = __expf(acc[mf][nfr][3]*sc);
            *(uint32_t*)&sstage[rl  ][cl] = packbf(e0, e1);
            *(uint32_t*)&sstage[rl+8][cl] = packbf(e2, e3);
            p0 += e0 + e1;
            p1 += e2 + e3;
        }
        p0 += __shfl_xor_sync(0xFFFFFFFFu, p0, 1);
        p0 += __shfl_xor_sync(0xFFFFFFFFu, p0, 2);
        p1 += __shfl_xor_sync(0xFFFFFFFFu, p1, 1);
        p1 += __shfl_xor_sync(0xFFFFFFFFu, p1, 2);
        if (tg == 0) {
            // wcol halves accumulate into [8] slots; wrow distinguishes rows
            spsum[wcol][rl    ] = p0;
            spsum[wcol][rl + 8] = p1;
        }
    }
    __syncthreads();
    if (tid < 128) {
        float s8 = 0.f;
        #pragma unroll
        for (int q=0; q<8; ++q) s8 += spsum[q][tid];
        g_psum[((size_t)b*NMB + (m0>>8))*Nn + n0 + tid] = s8;
    }
    #pragma unroll
    for (int it=0; it<8; ++it) {
        int idx = tid + 512*it;               // 4096 over 128 rows x 32 chunks
        int row = idx >> 5, c8 = idx & 31;
        *(uint4*)(g_attnb + (size_t)b*Nn*Nn + (size_t)(n0+row)*Nn + m0 + c8*8)
            = *(const uint4*)&sstage[row][c8*8];
    }
}

// ---------------------------------------------------------------------------
// Kernel 3: AV + fused rowsum (hoisted) + fused BN stats. 3-stage, K-step 64.
// ---------------------------------------------------------------------------
#define AV_VOFF  16384
#define AV_STAGE (16384 + 18432)
#define AV_RINV  (3*AV_STAGE)
#define AV_SMEM  (3*AV_STAGE + 512)

__global__ void __launch_bounds__(256) k_av(
    const float* __restrict__ xr, const float* __restrict__ xi,
    const float* __restrict__ gamma)
{
    extern __shared__ __align__(16) unsigned char dyn[];
    const uint32_t base = s2u(dyn);

    const int tid = threadIdx.x;
    const int w = tid >> 5, lane = tid & 31;
    const int gr = lane >> 2, tg = lane & 3;
    const int wm = w & 3, wn = w >> 2;
    const int n0 = blockIdx.x * 128;
    const int d0 = blockIdx.y * 64;
    const int b  = blockIdx.z;

    const __nv_bfloat16* Ab  = g_attnb + (size_t)b*Nn*Nn;
    const __nv_bfloat16* vp[2] = { g_v[0] + (size_t)b*Nn*Cc, g_v[1] + (size_t)b*Nn*Cc };

    float accr[2][4][4], acci[2][4][4];
    #pragma unroll
    for (int mf=0; mf<2; ++mf)
        #pragma unroll
        for (int nf=0; nf<4; ++nf)
            #pragma unroll
            for (int e=0; e<4; ++e){ accr[mf][nf][e]=0.f; acci[mf][nf][e]=0.f; }

    auto load_stage = [&](int s, int mk){
        const uint32_t st = base + s*AV_STAGE;
        #pragma unroll
        for (int it=0; it<4; ++it){
            int idx = tid + 256*it;
            int r = idx>>3, c = idx&7;
            cpa16(sw128(st, r, c), Ab + (size_t)(n0+r)*Nn + mk + c*8);
        }
        #pragma unroll
        for (int it=0; it<4; ++it){
            int idx = tid + 256*it;
            int p = idx>>9, r = (idx>>3)&63, c = idx&7;
            cpa16(st + AV_VOFF + p*9216 + r*144 + c*16,
                  vp[p] + (size_t)(mk+r)*Cc + d0 + c*8);
        }
        CP_COMMIT();
    };

    load_stage(0, 0);
    load_stage(1, 64);

    float* srinv = (float*)(dyn + AV_RINV);
    if (tid < 128) {
        float s = 0.f;
        #pragma unroll
        for (int mb=0; mb<NMB; ++mb)
            s += g_psum[((size_t)b*NMB + mb)*Nn + n0 + tid];
        srinv[tid] = 1.f / s;
    }

    const int NKT = Nn/64;
    for (int kt = 0; kt < NKT; ++kt) {
        const int s = kt % 3;
        if (kt < NKT-1) { CP_WAIT(1); } else { CP_WAIT(0); }
        __syncthreads();
        if (kt + 2 < NKT) load_stage((kt+2)%3, (kt+2)*64);

        const uint32_t st = base + s*AV_STAGE;
        #pragma unroll
        for (int ks=0; ks<64; ks+=16) {
            uint32_t a[2][4];
            #pragma unroll
            for (int mf=0; mf<2; ++mf) {
                int r = wm*32 + mf*16 + (lane&15);
                int c16 = (ks>>3) + (lane>>4);
                ldsm4(a[mf], sw128(st, r, c16));
            }
            #pragma unroll
            for (int nf2=0; nf2<2; ++nf2) {
                int cb = wn*32 + nf2*16;
                uint32_t bvr[4], bvi[4];
                uint32_t vaddr = st + AV_VOFF + (uint32_t)(ks + (lane&15))*144 + (uint32_t)(cb + (lane>>4)*8)*2;
                ldsm4t(bvr, vaddr);
                ldsm4t(bvi, vaddr + 9216);
                #pragma unroll
                for (int h=0; h<2; ++h) {
                    int nfr = nf2*2 + h;
                    #pragma unroll
                    for (int mf=0; mf<2; ++mf) {
                        mma16(accr[mf][nfr], a[mf], bvr + 2*h);
                        mma16(acci[mf][nfr], a[mf], bvi + 2*h);
                    }
                }
            }
        }
        __syncthreads();
    }

    float rin[2][2];
    #pragma unroll
    for (int mf=0; mf<2; ++mf) {
        rin[mf][0] = srinv[wm*32 + mf*16 + gr];
        rin[mf][1] = srinv[wm*32 + mf*16 + gr + 8];
    }
    const float gma = gamma[0];

    __nv_bfloat16 (*stage)[144] = (__nv_bfloat16(*)[144])dyn;
    const size_t basep = (size_t)b*Cc*Nn + (size_t)d0*Nn + n0;
    const int wi = b*18 + blockIdx.x;
    #pragma unroll
    for (int p=0; p<2; ++p) {
        __syncthreads();
        #pragma unroll
        for (int mf=0; mf<2; ++mf) {
            int rl = wm*32 + mf*16 + gr;
            #pragma unroll
            for (int nfr=0; nfr<4; ++nfr) {
                int cl = wn*32 + nfr*8 + 2*tg;
                float* acc = p ? acci[mf][nfr] : accr[mf][nfr];
                stage[cl  ][rl  ] = __float2bfloat16(acc[0]*rin[mf][0]);
                stage[cl+1][rl  ] = __float2bfloat16(acc[1]*rin[mf][0]);
                stage[cl  ][rl+8] = __float2bfloat16(acc[2]*rin[mf][1]);
                stage[cl+1][rl+8] = __float2bfloat16(acc[3]*rin[mf][1]);
            }
        }
        __syncthreads();
        #pragma unroll
        for (int it=0; it<4; ++it) {
            int idx = tid + 256*it;
            int dl = idx >> 4, c8 = idx & 15;
            *(uint4*)(g_outT[p] + basep + (size_t)dl*Nn + c8*8) = *(const uint4*)&stage[dl][c8*8];
        }
        {
            const float* x = p ? xi : xr;
            #pragma unroll
            for (int it=0; it<4; ++it) {
                const int dl = (tid >> 4) + it*16;
                const int c8 = tid & 15;
                const float* xp = x + (size_t)b*Cc*Nn + (size_t)(d0+dl)*Nn + n0 + c8*8;
                float4 xv0 = *(const float4*)xp;
                float4 xv1 = *(const float4*)(xp + 4);
                const __nv_bfloat16* sp = &stage[dl][c8*8];
                float xs[8] = {xv0.x,xv0.y,xv0.z,xv0.w,xv1.x,xv1.y,xv1.z,xv1.w};
                float s = 0.f, ss = 0.f;
                #pragma unroll
                for (int j=0;j<8;++j){
                    float z = xs[j] + gma*__bfloat162float(sp[j]);
                    s += z; ss += z*z;
                }
                #pragma unroll
                for (int off=1; off<16; off<<=1){
                    s  += __shfl_xor_sync(0xFFFFFFFFu, s,  off);
                    ss += __shfl_xor_sync(0xFFFFFFFFu, ss, off);
                }
                if ((tid & 15) == 0) {
                    g_bnps[p][d0+dl][wi][0] = s;
                    g_bnps[p][d0+dl][wi][1] = ss;
                }
            }
        }
    }
}

// ---------------------------------------------------------------------------
// Kernel 4: BN stats reduce -> mean, rstd
// ---------------------------------------------------------------------------
__global__ void __launch_bounds__(256) k_bnred()
{
    const int c = blockIdx.x, p = blockIdx.y;
    const int tid = threadIdx.x;
    float s = 0.f, ss = 0.f;
    if (tid < Bb*18) {
        s  = g_bnps[p][c][tid][0];
        ss = g_bnps[p][c][tid][1];
    }
    __shared__ float rs[256], rss[256];
    rs[tid] = s; rss[tid] = ss; __syncthreads();
    #pragma unroll
    for (int st = 128; st > 0; st >>= 1) {
        if (tid < st) { rs[tid] += rs[tid+st]; rss[tid] += rss[tid+st]; }
        __syncthreads();
    }
    if (tid == 0) {
        const float inv_cnt = 1.f / (float)Mtot;
        float mean = rs[0] * inv_cnt;
        float var  = rss[0] * inv_cnt - mean*mean;
        g_mean[p][c] = mean;
        g_rstd[p][c] = rsqrtf(var + EPSf);
    }
}

// ---------------------------------------------------------------------------
// Kernel 5: BN apply (8 elems/thread)
// ---------------------------------------------------------------------------
__global__ void __launch_bounds__(256) k_bnapply(
    const float* __restrict__ xr, const float* __restrict__ xi,
    const float* __restrict__ gamma,
    const float* __restrict__ bnwr, const float* __restrict__ bnbr,
    const float* __restrict__ bnwi, const float* __restrict__ bnbi,
    float* __restrict__ out)
{
    const size_t e = ((size_t)blockIdx.x*256 + threadIdx.x) * 8;
    const size_t half = (size_t)Bb*Cc*Nn;
    const int p = (e >= half) ? 1 : 0;
    const size_t rem = e - (size_t)p*half;
    const int c = (int)((rem / Nn) % Cc);

    const float* x = p ? xi : xr;
    const float g = gamma[0];
    const float wsc = (p ? bnwi[c] : bnwr[c]) * g_rstd[p][c];
    const float bia = (p ? bnbi[c] : bnbr[c]);
    const float mu = g_mean[p][c];

    float4 xv0 = *(const float4*)(x + rem);
    float4 xv1 = *(const float4*)(x + rem + 4);
    uint4 ou = *(const uint4*)(g_outT[p] + rem);
    float2 o01 = __bfloat1622float2(*reinterpret_cast<const __nv_bfloat162*>(&ou.x));
    float2 o23 = __bfloat1622float2(*reinterpret_cast<const __nv_bfloat162*>(&ou.y));
    float2 o45 = __bfloat1622float2(*reinterpret_cast<const __nv_bfloat162*>(&ou.z));
    float2 o67 = __bfloat1622float2(*reinterpret_cast<const __nv_bfloat162*>(&ou.w));

    float4 r0, r1;
    r0.x = (xv0.x + g*o01.x - mu) * wsc + bia;
    r0.y = (xv0.y + g*o01.y - mu) * wsc + bia;
    r0.z = (xv0.z + g*o23.x - mu) * wsc + bia;
    r0.w = (xv0.w + g*o23.y - mu) * wsc + bia;
    r1.x = (xv1.x + g*o45.x - mu) * wsc + bia;
    r1.y = (xv1.y + g*o45.y - mu) * wsc + bia;
    r1.z = (xv1.z + g*o67.x - mu) * wsc + bia;
    r1.w = (xv1.w + g*o67.y - mu) * wsc + bia;
    *(float4*)(out + e)     = r0;
    *(float4*)(out + e + 4) = r1;
}

// ---------------------------------------------------------------------------
// Launch
// ---------------------------------------------------------------------------
extern "C" void kernel_launch(void* const* d_in, const int* in_sizes, int n_in,
                              void* d_out, int out_size)
{
    const float* xr   = (const float*)d_in[0];
    const float* xi   = (const float*)d_in[1];
    const float* q_wr = (const float*)d_in[2];
    const float* q_wi = (const float*)d_in[3];
    const float* q_br = (const float*)d_in[4];
    const float* q_bi = (const float*)d_in[5];
    const float* k_wr = (const float*)d_in[6];
    const float* k_wi = (const float*)d_in[7];
    const float* k_br = (const float*)d_in[8];
    const float* k_bi = (const float*)d_in[9];
    const float* v_wr = (const float*)d_in[10];
    const float* v_wi = (const float*)d_in[11];
    const float* v_br = (const float*)d_in[12];
    const float* v_bi = (const float*)d_in[13];
    const float* gamma= (const float*)d_in[14];
    const float* bnwr = (const float*)d_in[15];
    const float* bnbr = (const float*)d_in[16];
    const float* bnwi = (const float*)d_in[17];
    const float* bnbi = (const float*)d_in[18];
    float* out = (float*)d_out;

    cudaFuncSetAttribute(k_proj,   cudaFuncAttributeMaxDynamicSharedMemorySize, PJ_SMEM);
    cudaFuncSetAttribute(k_scores, cudaFuncAttributeMaxDynamicSharedMemorySize, SC_SMEM);
    cudaFuncSetAttribute(k_av,     cudaFuncAttributeMaxDynamicSharedMemorySize, AV_SMEM);

    k_cvtall<<<(unsigned)(XBLKS + WBLKS), 256>>>(xr, xi, q_wr, q_wi, k_wr, k_wi, v_wr, v_wi);

    k_proj<<<dim3(Mtot/128, Cc/64, 3), 256, PJ_SMEM>>>(q_br, q_bi, k_br, k_bi, v_br, v_bi);

    k_scores<<<dim3(Nn/256, Nn/128, Bb), 512, SC_SMEM>>>();
    k_av<<<dim3(Nn/128, Cc/64, Bb), 256, AV_SMEM>>>(xr, xi, gamma);

    k_bnred<<<dim3(Cc, 2), 256>>>();
    k_bnapply<<<(2*(size_t)Bb*Cc*Nn/8)/256, 256>>>(xr, xi, gamma, bnwr, bnbr, bnwi, bnbi, out);
}